// round 10
// baseline (speedup 1.0000x reference)
#include <cuda_runtime.h>

#define NPTS 80
#define PITCH 84                        // 84 mod 16 == 4 -> conflict-free with 4-thread/row layout
#define NDELAYS 32
#define NPARAMS 256
#define IMG 6400
#define LAMBDA 0.03f
#define X_FLOATS (NDELAYS*IMG)          // 204800 floats for best_x
#define TF_REAL  (NDELAYS*IMG)          // 204800 floats for best tf (real-valued)
#define TF_TOTAL ((long long)NPARAMS * NDELAYS * IMG)   // 52428800 floats
#define NTHR 320                        // 4 threads per row

// ---------------- workspace ----------------
__device__ float2 g_Yf[NDELAYS * IMG];
__device__ float  g_partial[NPARAMS * NDELAYS];
__device__ int    g_best;

__device__ __forceinline__ float gld(const float* p, long long i, long long imax) {
    return (i >= 0 && i <= imax) ? p[i] : 0.f;
}

// ---------------- 16-point FFT in registers (U=+1 inverse, U=-1 forward, unscaled) ----------------
template<int U>
__device__ __forceinline__ void fft16r(float2* v) {
    const float C16[8] = {1.f, 0.9238795325112867f, 0.7071067811865476f, 0.3826834323650898f,
                          0.f, -0.3826834323650898f, -0.7071067811865476f, -0.9238795325112867f};
    const float S16[8] = {0.f, 0.3826834323650898f, 0.7071067811865476f, 0.9238795325112867f,
                          1.f, 0.9238795325112867f, 0.7071067811865476f, 0.3826834323650898f};
    float2 t;
    t = v[1];  v[1]  = v[8];  v[8]  = t;
    t = v[2];  v[2]  = v[4];  v[4]  = t;
    t = v[3];  v[3]  = v[12]; v[12] = t;
    t = v[5];  v[5]  = v[10]; v[10] = t;
    t = v[7];  v[7]  = v[14]; v[14] = t;
    t = v[11]; v[11] = v[13]; v[13] = t;
#pragma unroll
    for (int len = 2; len <= 16; len <<= 1) {
        const int half = len >> 1;
        const int step = 16 / len;
#pragma unroll
        for (int i = 0; i < 16; i += len) {
#pragma unroll
            for (int j = 0; j < half; j++) {
                float wc = C16[j * step];
                float ws = (float)U * S16[j * step];
                float2 a = v[i + j], b = v[i + j + half];
                float tr = b.x * wc - b.y * ws;
                float ti = b.x * ws + b.y * wc;
                v[i + j]        = make_float2(a.x + tr, a.y + ti);
                v[i + j + half] = make_float2(a.x - tr, a.y - ti);
            }
        }
    }
}

// ---------------- 80x80 2D FFT, 4 threads per row (320 threads), in place on X, T scratch ----------------
template<int U>
__device__ void fft2d80(float2* X, float2* T, const float2* w80, int tid) {
    const float C5[5] = {1.f, 0.30901699437494745f, -0.8090169943749475f,
                         -0.8090169943749475f, 0.30901699437494745f};
    const float S5[5] = {0.f, 0.9510565162951535f, 0.5877852522924731f,
                         -0.5877852522924731f, -0.9510565162951535f};
    const int row = tid >> 2;       // 0..79
    const int j   = tid & 3;        // 0..3
#pragma unroll
    for (int pass = 0; pass < 2; ++pass) {
        // stage 1: radix-5 DFT + W80 twiddle over 4 of the 16 n2-columns
        // bank(f2) = 4*row + n2 (mod 16), n2 = j + 4m (m uniform) -> conflict-free
        {
            const float2* s = X + row * PITCH;
            float2* trow = T + row * PITCH;
#pragma unroll
            for (int m = 0; m < 4; m++) {
                const int n2 = j + 4 * m;
                float2 c[5];
#pragma unroll
                for (int n1 = 0; n1 < 5; n1++) c[n1] = s[16 * n1 + n2];
#pragma unroll
                for (int k = 0; k < 5; k++) {
                    float re = c[0].x, im = c[0].y;
#pragma unroll
                    for (int n = 1; n < 5; n++) {
                        int mm = (n * k) % 5;
                        float wc = C5[mm], ws = (float)U * S5[mm];
                        re += c[n].x * wc - c[n].y * ws;
                        im += c[n].x * ws + c[n].y * wc;
                    }
                    float2 dv = make_float2(re, im);
                    if (k > 0) {
                        float wc = w80[n2 * k].x, ws = (float)U * w80[n2 * k].y;
                        dv = make_float2(dv.x * wc - dv.y * ws, dv.x * ws + dv.y * wc);
                    }
                    trow[k * 16 + n2] = dv;
                }
            }
        }
        __syncthreads();
        // stage 2: radix-16 FFTs; j=0,1,2 do k1=j, j=3 does k1=3,4.
        // reads rotated by j so bank = 4*row + (n2+j)&15 is injective per instruction.
        {
            const float2* trow = T + row * PITCH;
            const int nk = (j == 3) ? 2 : 1;
#pragma unroll
            for (int q = 0; q < 2; q++) {
                if (q >= nk) break;
                const int k1 = (j == 3) ? (3 + q) : j;
                float2 v[16];
#pragma unroll
                for (int t = 0; t < 16; t++) {
                    const int n2 = (t + j) & 15;
                    v[n2] = trow[k1 * 16 + n2];
                }
                fft16r<U>(v);
#pragma unroll
                for (int k2 = 0; k2 < 16; k2++) X[(k1 + 5 * k2) * PITCH + row] = v[k2];
            }
        }
        __syncthreads();
    }
}

// ---------------- deterministic block reduce (blockDim = NTHR = 10 warps) ----------------
__device__ float blockReduceSum(float v, float* red, int tid) {
#pragma unroll
    for (int o = 16; o > 0; o >>= 1) v += __shfl_down_sync(0xffffffffu, v, o);
    if ((tid & 31) == 0) red[tid >> 5] = v;
    __syncthreads();
    if (tid == 0) {
        float s = 0.f;
        for (int w = 0; w < NTHR / 32; w++) s += red[w];
        red[0] = s;
    }
    __syncthreads();
    float r = red[0];
    __syncthreads();
    return r;
}

#define SMEM_F2 (2 * NPTS * PITCH + 80)
#define SMEM_BYTES (SMEM_F2 * sizeof(float2) + 64 * sizeof(float))

__device__ __forceinline__ void fill_w80(float2* w80, int tid) {
    if (tid < 80) {
        float sv, cv;
        sincospif((float)tid * (1.0f / 40.0f), &sv, &cv);   // 2*pi*tid/80
        w80[tid] = make_float2(cv, sv);
    }
}

// ---------------- kernel 1: Yf = fft2(y), 32 blocks ----------------
__global__ void __launch_bounds__(NTHR, 2) yf_kernel(const float* __restrict__ y) {
    extern __shared__ float sm[];
    float2* A = (float2*)sm;
    float2* B = A + NPTS * PITCH;
    float2* w80 = B + NPTS * PITCH;
    int tid = threadIdx.x;
    int d = blockIdx.x;
    fill_w80(w80, tid);
    for (int idx = tid; idx < IMG; idx += NTHR)
        A[(idx / 80) * PITCH + (idx % 80)] = make_float2(gld(y, (long long)d * IMG + idx, X_FLOATS - 1), 0.f);
    __syncthreads();
    fft2d80<-1>(A, B, w80, tid);
    for (int idx = tid; idx < IMG; idx += NTHR)
        g_Yf[d * IMG + idx] = A[(idx / 80) * PITCH + (idx % 80)];
}

// ---------------- kernel 2: per-(p,d) partial loss, 8192 blocks (TF is REAL float32) ----------------
__global__ void __launch_bounds__(NTHR, 2) loss_kernel(const float* __restrict__ tf, const float* __restrict__ y) {
    extern __shared__ float sm[];
    float2* A = (float2*)sm;
    float2* B = A + NPTS * PITCH;
    float2* w80 = B + NPTS * PITCH;
    float* red = (float*)(w80 + 80);
    int tid = threadIdx.x;
    int pd = blockIdx.x;
    int d = pd & 31;
    fill_w80(w80, tid);
    long long base = (long long)pd * IMG;
    for (int idx = tid; idx < IMG; idx += NTHR)
        A[(idx / 80) * PITCH + (idx % 80)] = make_float2(gld(tf, base + idx, TF_TOTAL - 1), 0.f);
    __syncthreads();
    fft2d80<1>(A, B, w80, tid);          // unscaled ifft2(TF); 1/6400 cancels in normalization
    float s = 0.f;
    for (int idx = tid; idx < IMG; idx += NTHR) {
        float2 v = A[(idx / 80) * PITCH + (idx % 80)];
        s += sqrtf(v.x * v.x + v.y * v.y);
    }
    float S = blockReduceSum(s, red, tid);
    float invS = 1.0f / S;
    const float2* yf = g_Yf + d * IMG;
    for (int idx = tid; idx < IMG; idx += NTHR) {
        int i = idx / 80, j = idx % 80;
        int si = (i >= 40) ? i - 40 : i + 40;
        int sj = (j >= 40) ? j - 40 : j + 40;
        float2 a = A[si * PITCH + sj];
        float m = sqrtf(a.x * a.x + a.y * a.y) * invS;   // psf (shifted, normalized)
        float2 f = yf[idx];
        B[i * PITCH + j] = make_float2(m * f.x, m * f.y);
    }
    __syncthreads();
    fft2d80<1>(B, A, w80, tid);          // unscaled ifft2(psf * Yf)
    float acc = 0.f;
    for (int idx = tid; idx < IMG; idx += NTHR) {
        int i = idx / 80, j = idx % 80;
        int si = (i >= 40) ? i - 40 : i + 40;
        int sj = (j >= 40) ? j - 40 : j + 40;
        float2 v = B[si * PITCH + sj];
        float yh = sqrtf(v.x * v.x + v.y * v.y) * (1.0f / 6400.0f);
        float df = gld(y, (long long)d * IMG + idx, X_FLOATS - 1) - yh;
        acc += df * df;
    }
    float tot = blockReduceSum(acc, red, tid);
    if (tid == 0) g_partial[pd] = tot;
}

// ---------------- kernel 3: reduce + argmin ----------------
__global__ void argmin_kernel(const float* __restrict__ params, float* __restrict__ out) {
    __shared__ float sl[NPARAMS];
    __shared__ int   si[NPARAMS];
    int tid = threadIdx.x;
    float s = 0.f;
    for (int d = 0; d < NDELAYS; d++) s += g_partial[tid * NDELAYS + d];
    float loss = s / (float)(NDELAYS * IMG);
    sl[tid] = loss; si[tid] = tid;
    __syncthreads();
    for (int st = 128; st > 0; st >>= 1) {
        if (tid < st) {
            float lo = sl[tid + st];
            if (lo < sl[tid] || (lo == sl[tid] && si[tid + st] < si[tid])) {
                sl[tid] = lo; si[tid] = si[tid + st];
            }
        }
        __syncthreads();
    }
    if (tid == 0) {
        g_best = si[0];
        out[X_FLOATS + TF_REAL + 0] = gld(params, (long long)si[0] * 3 + 0, 767);
        out[X_FLOATS + TF_REAL + 1] = gld(params, (long long)si[0] * 3 + 1, 767);
        out[X_FLOATS + TF_REAL + 2] = gld(params, (long long)si[0] * 3 + 2, 767);
        out[X_FLOATS + TF_REAL + 3] = sl[0];
    }
}

// ---------------- kernel 4: copy best TF (real floats) ----------------
__global__ void copytf_kernel(const float* __restrict__ tf, float* __restrict__ out) {
    long long base = (long long)g_best * TF_REAL;
    for (int i = blockIdx.x * blockDim.x + threadIdx.x; i < TF_REAL; i += gridDim.x * blockDim.x)
        out[X_FLOATS + i] = gld(tf, base + i, TF_TOTAL - 1);
}

// ---------------- kernel 5: best_x (Wiener deconv for winner), 32 blocks ----------------
__global__ void __launch_bounds__(NTHR, 2) bestx_kernel(const float* __restrict__ tf, float* __restrict__ out) {
    extern __shared__ float sm[];
    float2* A = (float2*)sm;
    float2* B = A + NPTS * PITCH;
    float2* w80 = B + NPTS * PITCH;
    float* red = (float*)(w80 + 80);
    int tid = threadIdx.x;
    int d = blockIdx.x;
    fill_w80(w80, tid);
    long long base = ((long long)g_best * NDELAYS + d) * IMG;
    for (int idx = tid; idx < IMG; idx += NTHR)
        A[(idx / 80) * PITCH + (idx % 80)] = make_float2(gld(tf, base + idx, TF_TOTAL - 1), 0.f);
    __syncthreads();
    fft2d80<1>(A, B, w80, tid);
    float s = 0.f;
    for (int idx = tid; idx < IMG; idx += NTHR) {
        float2 v = A[(idx / 80) * PITCH + (idx % 80)];
        s += sqrtf(v.x * v.x + v.y * v.y);
    }
    float S = blockReduceSum(s, red, tid);
    float invS = 1.0f / S;
    for (int idx = tid; idx < IMG; idx += NTHR) {
        int i = idx / 80, j = idx % 80;
        int si = (i >= 40) ? i - 40 : i + 40;
        int sj = (j >= 40) ? j - 40 : j + 40;
        float2 a = A[si * PITCH + sj];
        B[i * PITCH + j] = make_float2(sqrtf(a.x * a.x + a.y * a.y) * invS, 0.f);
    }
    __syncthreads();
    fft2d80<-1>(B, A, w80, tid);         // H = fft2(psf)
    const float2* yf = g_Yf + d * IMG;
    for (int idx = tid; idx < IMG; idx += NTHR) {
        int i = idx / 80, j = idx % 80;
        float2 h = B[i * PITCH + j];
        float2 f = yf[idx];
        float den = h.x * h.x + h.y * h.y + LAMBDA;
        B[i * PITCH + j] = make_float2((h.x * f.x + h.y * f.y) / den,
                                       (h.x * f.y - h.y * f.x) / den);
    }
    __syncthreads();
    fft2d80<1>(B, A, w80, tid);
    for (int idx = tid; idx < IMG; idx += NTHR) {
        int i = idx / 80, j = idx % 80;
        int si = (i >= 40) ? i - 40 : i + 40;
        int sj = (j >= 40) ? j - 40 : j + 40;
        float2 v = B[si * PITCH + sj];
        out[d * IMG + idx] = sqrtf(v.x * v.x + v.y * v.y) * (1.0f / 6400.0f);
    }
}

// ---------------- launcher ----------------
extern "C" void kernel_launch(void* const* d_in, const int* in_sizes, int n_in,
                              void* d_out, int out_size) {
    (void)in_sizes; (void)out_size;
    if (n_in < 3 || d_in == nullptr || d_out == nullptr) return;

    const float* y      = (const float*)d_in[0];   // 204800 floats
    const float* tf     = (const float*)d_in[1];   // 52428800 floats (TF real: cos(k(d-w)))
    const float* params = (const float*)d_in[2];   // 768 floats
    float* out = (float*)d_out;                    // 409604 floats: [x | tf | params | loss]

    cudaFuncSetAttribute(yf_kernel,    cudaFuncAttributeMaxDynamicSharedMemorySize, (int)SMEM_BYTES);
    cudaFuncSetAttribute(loss_kernel,  cudaFuncAttributeMaxDynamicSharedMemorySize, (int)SMEM_BYTES);
    cudaFuncSetAttribute(bestx_kernel, cudaFuncAttributeMaxDynamicSharedMemorySize, (int)SMEM_BYTES);

    yf_kernel<<<NDELAYS, NTHR, SMEM_BYTES>>>(y);
    loss_kernel<<<NPARAMS * NDELAYS, NTHR, SMEM_BYTES>>>(tf, y);
    argmin_kernel<<<1, NPARAMS>>>(params, out);
    copytf_kernel<<<256, 256>>>(tf, out);
    bestx_kernel<<<NDELAYS, NTHR, SMEM_BYTES>>>(tf, out);
}

// round 11
// speedup vs baseline: 1.6350x; 1.6350x over previous
#include <cuda_runtime.h>

#define NPTS 80
#define PITCH 84                        // 84 mod 16 == 4 -> conflict-free with 4-thread/row layout
#define NDELAYS 32
#define NPARAMS 256
#define IMG 6400
#define LAMBDA 0.03f
#define X_FLOATS (NDELAYS*IMG)          // 204800 floats for best_x
#define TF_REAL  (NDELAYS*IMG)          // 204800 floats for best tf (real-valued)
#define TF_TOTAL ((long long)NPARAMS * NDELAYS * IMG)   // 52428800 floats
#define NTHR 320                        // 4 threads per row

// ---------------- workspace ----------------
__device__ float2 g_Yf[NDELAYS * IMG];
__device__ float  g_partial[NPARAMS * NDELAYS];
__device__ int    g_best;

__device__ __forceinline__ float gld(const float* p, long long i, long long imax) {
    return (i >= 0 && i <= imax) ? p[i] : 0.f;
}

// ---------------- 16-point FFT in registers (U=+1 inverse, U=-1 forward, unscaled) ----------------
template<int U>
__device__ __forceinline__ void fft16r(float2* v) {
    const float C16[8] = {1.f, 0.9238795325112867f, 0.7071067811865476f, 0.3826834323650898f,
                          0.f, -0.3826834323650898f, -0.7071067811865476f, -0.9238795325112867f};
    const float S16[8] = {0.f, 0.3826834323650898f, 0.7071067811865476f, 0.9238795325112867f,
                          1.f, 0.9238795325112867f, 0.7071067811865476f, 0.3826834323650898f};
    float2 t;
    t = v[1];  v[1]  = v[8];  v[8]  = t;
    t = v[2];  v[2]  = v[4];  v[4]  = t;
    t = v[3];  v[3]  = v[12]; v[12] = t;
    t = v[5];  v[5]  = v[10]; v[10] = t;
    t = v[7];  v[7]  = v[14]; v[14] = t;
    t = v[11]; v[11] = v[13]; v[13] = t;
#pragma unroll
    for (int len = 2; len <= 16; len <<= 1) {
        const int half = len >> 1;
        const int step = 16 / len;
#pragma unroll
        for (int i = 0; i < 16; i += len) {
#pragma unroll
            for (int j = 0; j < half; j++) {
                float wc = C16[j * step];
                float ws = (float)U * S16[j * step];
                float2 a = v[i + j], b = v[i + j + half];
                float tr = b.x * wc - b.y * ws;
                float ti = b.x * ws + b.y * wc;
                v[i + j]        = make_float2(a.x + tr, a.y + ti);
                v[i + j + half] = make_float2(a.x - tr, a.y - ti);
            }
        }
    }
}

// ---------------- 80x80 2D FFT, 4 threads per row (320 threads), in place on X, T scratch ----------------
// T uses a k-skewed layout: value (k, n2) lives at trow[k*16 + ((n2 + k) & 15)].
// This makes BOTH stage-1 writes and stage-2 reads conflict-free with PITCH=84,
// while register arrays stay compile-time indexed (no local-memory spill).
template<int U>
__device__ void fft2d80(float2* X, float2* T, const float2* w80, int tid) {
    const float C5[5] = {1.f, 0.30901699437494745f, -0.8090169943749475f,
                         -0.8090169943749475f, 0.30901699437494745f};
    const float S5[5] = {0.f, 0.9510565162951535f, 0.5877852522924731f,
                         -0.5877852522924731f, -0.9510565162951535f};
    const int row = tid >> 2;       // 0..79
    const int j   = tid & 3;        // 0..3
#pragma unroll
    for (int pass = 0; pass < 2; ++pass) {
        // stage 1: radix-5 DFT + W80 twiddle over 4 of the 16 n2-columns
        {
            const float2* s = X + row * PITCH;
            float2* trow = T + row * PITCH;
#pragma unroll
            for (int m = 0; m < 4; m++) {
                const int n2 = j + 4 * m;
                float2 c[5];
#pragma unroll
                for (int n1 = 0; n1 < 5; n1++) c[n1] = s[16 * n1 + n2];
#pragma unroll
                for (int k = 0; k < 5; k++) {
                    float re = c[0].x, im = c[0].y;
#pragma unroll
                    for (int n = 1; n < 5; n++) {
                        int mm = (n * k) % 5;
                        float wc = C5[mm], ws = (float)U * S5[mm];
                        re += c[n].x * wc - c[n].y * ws;
                        im += c[n].x * ws + c[n].y * wc;
                    }
                    float2 dv = make_float2(re, im);
                    if (k > 0) {
                        float wc = w80[n2 * k].x, ws = (float)U * w80[n2 * k].y;
                        dv = make_float2(dv.x * wc - dv.y * ws, dv.x * ws + dv.y * wc);
                    }
                    trow[k * 16 + ((n2 + k) & 15)] = dv;   // skewed store
                }
            }
        }
        __syncthreads();
        // stage 2: radix-16 FFTs; j=0,1,2 do k1=j, j=3 does k1=3,4
        {
            const float2* trow = T + row * PITCH;
            const int nk = (j == 3) ? 2 : 1;
#pragma unroll
            for (int q = 0; q < 2; q++) {
                if (q >= nk) break;
                const int k1 = (j == 3) ? (3 + q) : j;
                float2 v[16];
#pragma unroll
                for (int t = 0; t < 16; t++)
                    v[t] = trow[k1 * 16 + ((t + k1) & 15)];   // skewed load, v[] compile-time indexed
                fft16r<U>(v);
#pragma unroll
                for (int k2 = 0; k2 < 16; k2++) X[(k1 + 5 * k2) * PITCH + row] = v[k2];
            }
        }
        __syncthreads();
    }
}

// ---------------- deterministic block reduce (blockDim = NTHR = 10 warps) ----------------
__device__ float blockReduceSum(float v, float* red, int tid) {
#pragma unroll
    for (int o = 16; o > 0; o >>= 1) v += __shfl_down_sync(0xffffffffu, v, o);
    if ((tid & 31) == 0) red[tid >> 5] = v;
    __syncthreads();
    if (tid == 0) {
        float s = 0.f;
        for (int w = 0; w < NTHR / 32; w++) s += red[w];
        red[0] = s;
    }
    __syncthreads();
    float r = red[0];
    __syncthreads();
    return r;
}

#define SMEM_F2 (2 * NPTS * PITCH + 80)
#define SMEM_BYTES (SMEM_F2 * sizeof(float2) + 64 * sizeof(float))

__device__ __forceinline__ void fill_w80(float2* w80, int tid) {
    if (tid < 80) {
        float sv, cv;
        sincospif((float)tid * (1.0f / 40.0f), &sv, &cv);   // 2*pi*tid/80
        w80[tid] = make_float2(cv, sv);
    }
}

// ---------------- kernel 1: Yf = fft2(y), 32 blocks ----------------
__global__ void __launch_bounds__(NTHR, 2) yf_kernel(const float* __restrict__ y) {
    extern __shared__ float sm[];
    float2* A = (float2*)sm;
    float2* B = A + NPTS * PITCH;
    float2* w80 = B + NPTS * PITCH;
    int tid = threadIdx.x;
    int d = blockIdx.x;
    fill_w80(w80, tid);
    for (int idx = tid; idx < IMG; idx += NTHR)
        A[(idx / 80) * PITCH + (idx % 80)] = make_float2(gld(y, (long long)d * IMG + idx, X_FLOATS - 1), 0.f);
    __syncthreads();
    fft2d80<-1>(A, B, w80, tid);
    for (int idx = tid; idx < IMG; idx += NTHR)
        g_Yf[d * IMG + idx] = A[(idx / 80) * PITCH + (idx % 80)];
}

// ---------------- kernel 2: per-(p,d) partial loss, 8192 blocks (TF is REAL float32) ----------------
__global__ void __launch_bounds__(NTHR, 2) loss_kernel(const float* __restrict__ tf, const float* __restrict__ y) {
    extern __shared__ float sm[];
    float2* A = (float2*)sm;
    float2* B = A + NPTS * PITCH;
    float2* w80 = B + NPTS * PITCH;
    float* red = (float*)(w80 + 80);
    int tid = threadIdx.x;
    int pd = blockIdx.x;
    int d = pd & 31;
    fill_w80(w80, tid);
    long long base = (long long)pd * IMG;
    for (int idx = tid; idx < IMG; idx += NTHR)
        A[(idx / 80) * PITCH + (idx % 80)] = make_float2(gld(tf, base + idx, TF_TOTAL - 1), 0.f);
    __syncthreads();
    fft2d80<1>(A, B, w80, tid);          // unscaled ifft2(TF); 1/6400 cancels in normalization
    float s = 0.f;
    for (int idx = tid; idx < IMG; idx += NTHR) {
        float2 v = A[(idx / 80) * PITCH + (idx % 80)];
        s += sqrtf(v.x * v.x + v.y * v.y);
    }
    float S = blockReduceSum(s, red, tid);
    float invS = 1.0f / S;
    const float2* yf = g_Yf + d * IMG;
    for (int idx = tid; idx < IMG; idx += NTHR) {
        int i = idx / 80, j = idx % 80;
        int si = (i >= 40) ? i - 40 : i + 40;
        int sj = (j >= 40) ? j - 40 : j + 40;
        float2 a = A[si * PITCH + sj];
        float m = sqrtf(a.x * a.x + a.y * a.y) * invS;   // psf (shifted, normalized)
        float2 f = yf[idx];
        B[i * PITCH + j] = make_float2(m * f.x, m * f.y);
    }
    __syncthreads();
    fft2d80<1>(B, A, w80, tid);          // unscaled ifft2(psf * Yf)
    float acc = 0.f;
    for (int idx = tid; idx < IMG; idx += NTHR) {
        int i = idx / 80, j = idx % 80;
        int si = (i >= 40) ? i - 40 : i + 40;
        int sj = (j >= 40) ? j - 40 : j + 40;
        float2 v = B[si * PITCH + sj];
        float yh = sqrtf(v.x * v.x + v.y * v.y) * (1.0f / 6400.0f);
        float df = gld(y, (long long)d * IMG + idx, X_FLOATS - 1) - yh;
        acc += df * df;
    }
    float tot = blockReduceSum(acc, red, tid);
    if (tid == 0) g_partial[pd] = tot;
}

// ---------------- kernel 3: reduce + argmin ----------------
__global__ void argmin_kernel(const float* __restrict__ params, float* __restrict__ out) {
    __shared__ float sl[NPARAMS];
    __shared__ int   si[NPARAMS];
    int tid = threadIdx.x;
    float s = 0.f;
    for (int d = 0; d < NDELAYS; d++) s += g_partial[tid * NDELAYS + d];
    float loss = s / (float)(NDELAYS * IMG);
    sl[tid] = loss; si[tid] = tid;
    __syncthreads();
    for (int st = 128; st > 0; st >>= 1) {
        if (tid < st) {
            float lo = sl[tid + st];
            if (lo < sl[tid] || (lo == sl[tid] && si[tid + st] < si[tid])) {
                sl[tid] = lo; si[tid] = si[tid + st];
            }
        }
        __syncthreads();
    }
    if (tid == 0) {
        g_best = si[0];
        out[X_FLOATS + TF_REAL + 0] = gld(params, (long long)si[0] * 3 + 0, 767);
        out[X_FLOATS + TF_REAL + 1] = gld(params, (long long)si[0] * 3 + 1, 767);
        out[X_FLOATS + TF_REAL + 2] = gld(params, (long long)si[0] * 3 + 2, 767);
        out[X_FLOATS + TF_REAL + 3] = sl[0];
    }
}

// ---------------- kernel 4: copy best TF (real floats) ----------------
__global__ void copytf_kernel(const float* __restrict__ tf, float* __restrict__ out) {
    long long base = (long long)g_best * TF_REAL;
    for (int i = blockIdx.x * blockDim.x + threadIdx.x; i < TF_REAL; i += gridDim.x * blockDim.x)
        out[X_FLOATS + i] = gld(tf, base + i, TF_TOTAL - 1);
}

// ---------------- kernel 5: best_x (Wiener deconv for winner), 32 blocks ----------------
__global__ void __launch_bounds__(NTHR, 2) bestx_kernel(const float* __restrict__ tf, float* __restrict__ out) {
    extern __shared__ float sm[];
    float2* A = (float2*)sm;
    float2* B = A + NPTS * PITCH;
    float2* w80 = B + NPTS * PITCH;
    float* red = (float*)(w80 + 80);
    int tid = threadIdx.x;
    int d = blockIdx.x;
    fill_w80(w80, tid);
    long long base = ((long long)g_best * NDELAYS + d) * IMG;
    for (int idx = tid; idx < IMG; idx += NTHR)
        A[(idx / 80) * PITCH + (idx % 80)] = make_float2(gld(tf, base + idx, TF_TOTAL - 1), 0.f);
    __syncthreads();
    fft2d80<1>(A, B, w80, tid);
    float s = 0.f;
    for (int idx = tid; idx < IMG; idx += NTHR) {
        float2 v = A[(idx / 80) * PITCH + (idx % 80)];
        s += sqrtf(v.x * v.x + v.y * v.y);
    }
    float S = blockReduceSum(s, red, tid);
    float invS = 1.0f / S;
    for (int idx = tid; idx < IMG; idx += NTHR) {
        int i = idx / 80, j = idx % 80;
        int si = (i >= 40) ? i - 40 : i + 40;
        int sj = (j >= 40) ? j - 40 : j + 40;
        float2 a = A[si * PITCH + sj];
        B[i * PITCH + j] = make_float2(sqrtf(a.x * a.x + a.y * a.y) * invS, 0.f);
    }
    __syncthreads();
    fft2d80<-1>(B, A, w80, tid);         // H = fft2(psf)
    const float2* yf = g_Yf + d * IMG;
    for (int idx = tid; idx < IMG; idx += NTHR) {
        int i = idx / 80, j = idx % 80;
        float2 h = B[i * PITCH + j];
        float2 f = yf[idx];
        float den = h.x * h.x + h.y * h.y + LAMBDA;
        B[i * PITCH + j] = make_float2((h.x * f.x + h.y * f.y) / den,
                                       (h.x * f.y - h.y * f.x) / den);
    }
    __syncthreads();
    fft2d80<1>(B, A, w80, tid);
    for (int idx = tid; idx < IMG; idx += NTHR) {
        int i = idx / 80, j = idx % 80;
        int si = (i >= 40) ? i - 40 : i + 40;
        int sj = (j >= 40) ? j - 40 : j + 40;
        float2 v = B[si * PITCH + sj];
        out[d * IMG + idx] = sqrtf(v.x * v.x + v.y * v.y) * (1.0f / 6400.0f);
    }
}

// ---------------- launcher ----------------
extern "C" void kernel_launch(void* const* d_in, const int* in_sizes, int n_in,
                              void* d_out, int out_size) {
    (void)in_sizes; (void)out_size;
    if (n_in < 3 || d_in == nullptr || d_out == nullptr) return;

    const float* y      = (const float*)d_in[0];   // 204800 floats
    const float* tf     = (const float*)d_in[1];   // 52428800 floats (TF real: cos(k(d-w)))
    const float* params = (const float*)d_in[2];   // 768 floats
    float* out = (float*)d_out;                    // 409604 floats: [x | tf | params | loss]

    cudaFuncSetAttribute(yf_kernel,    cudaFuncAttributeMaxDynamicSharedMemorySize, (int)SMEM_BYTES);
    cudaFuncSetAttribute(loss_kernel,  cudaFuncAttributeMaxDynamicSharedMemorySize, (int)SMEM_BYTES);
    cudaFuncSetAttribute(bestx_kernel, cudaFuncAttributeMaxDynamicSharedMemorySize, (int)SMEM_BYTES);

    yf_kernel<<<NDELAYS, NTHR, SMEM_BYTES>>>(y);
    loss_kernel<<<NPARAMS * NDELAYS, NTHR, SMEM_BYTES>>>(tf, y);
    argmin_kernel<<<1, NPARAMS>>>(params, out);
    copytf_kernel<<<256, 256>>>(tf, out);
    bestx_kernel<<<NDELAYS, NTHR, SMEM_BYTES>>>(tf, out);
}

// round 12
// speedup vs baseline: 2.9524x; 1.8058x over previous
#include <cuda_runtime.h>

#define NPTS 80
#define PITCH 84                        // 84 mod 16 == 4 -> conflict-free with 4-thread/row layout
#define NDELAYS 32
#define NPARAMS 256
#define IMG 6400
#define LAMBDA 0.03f
#define X_FLOATS (NDELAYS*IMG)          // 204800 floats for best_x
#define TF_REAL  (NDELAYS*IMG)          // 204800 floats for best tf (real-valued)
#define TF_TOTAL ((long long)NPARAMS * NDELAYS * IMG)   // 52428800 floats
#define NTHR 320                        // 4 threads per row

// ---------------- workspace ----------------
__device__ float2 g_Yf[NDELAYS * IMG];
__device__ float  g_partial[NPARAMS * NDELAYS];
__device__ int    g_best;

__device__ __forceinline__ float gld(const float* p, long long i, long long imax) {
    return (i >= 0 && i <= imax) ? p[i] : 0.f;
}

// ---------------- 16-point FFT in registers (U=+1 inverse, U=-1 forward, unscaled) ----------------
template<int U>
__device__ __forceinline__ void fft16r(float2* v) {
    const float C16[8] = {1.f, 0.9238795325112867f, 0.7071067811865476f, 0.3826834323650898f,
                          0.f, -0.3826834323650898f, -0.7071067811865476f, -0.9238795325112867f};
    const float S16[8] = {0.f, 0.3826834323650898f, 0.7071067811865476f, 0.9238795325112867f,
                          1.f, 0.9238795325112867f, 0.7071067811865476f, 0.3826834323650898f};
    float2 t;
    t = v[1];  v[1]  = v[8];  v[8]  = t;
    t = v[2];  v[2]  = v[4];  v[4]  = t;
    t = v[3];  v[3]  = v[12]; v[12] = t;
    t = v[5];  v[5]  = v[10]; v[10] = t;
    t = v[7];  v[7]  = v[14]; v[14] = t;
    t = v[11]; v[11] = v[13]; v[13] = t;
#pragma unroll
    for (int len = 2; len <= 16; len <<= 1) {
        const int half = len >> 1;
        const int step = 16 / len;
#pragma unroll
        for (int i = 0; i < 16; i += len) {
#pragma unroll
            for (int j = 0; j < half; j++) {
                float wc = C16[j * step];
                float ws = (float)U * S16[j * step];
                float2 a = v[i + j], b = v[i + j + half];
                float tr = b.x * wc - b.y * ws;
                float ti = b.x * ws + b.y * wc;
                v[i + j]        = make_float2(a.x + tr, a.y + ti);
                v[i + j + half] = make_float2(a.x - tr, a.y - ti);
            }
        }
    }
}

// ---------------- 80x80 2D FFT, 4 threads per row (320 threads), in place on X, T scratch ----------------
// T uses a k-skewed layout: value (k, n2) lives at trow[k*16 + ((n2 + k) & 15)].
template<int U>
__device__ void fft2d80(float2* X, float2* T, const float2* w80, int tid) {
    const float C5[5] = {1.f, 0.30901699437494745f, -0.8090169943749475f,
                         -0.8090169943749475f, 0.30901699437494745f};
    const float S5[5] = {0.f, 0.9510565162951535f, 0.5877852522924731f,
                         -0.5877852522924731f, -0.9510565162951535f};
    const int row = tid >> 2;       // 0..79
    const int j   = tid & 3;        // 0..3
#pragma unroll
    for (int pass = 0; pass < 2; ++pass) {
        {
            const float2* s = X + row * PITCH;
            float2* trow = T + row * PITCH;
#pragma unroll
            for (int m = 0; m < 4; m++) {
                const int n2 = j + 4 * m;
                float2 c[5];
#pragma unroll
                for (int n1 = 0; n1 < 5; n1++) c[n1] = s[16 * n1 + n2];
#pragma unroll
                for (int k = 0; k < 5; k++) {
                    float re = c[0].x, im = c[0].y;
#pragma unroll
                    for (int n = 1; n < 5; n++) {
                        int mm = (n * k) % 5;
                        float wc = C5[mm], ws = (float)U * S5[mm];
                        re += c[n].x * wc - c[n].y * ws;
                        im += c[n].x * ws + c[n].y * wc;
                    }
                    float2 dv = make_float2(re, im);
                    if (k > 0) {
                        float wc = w80[n2 * k].x, ws = (float)U * w80[n2 * k].y;
                        dv = make_float2(dv.x * wc - dv.y * ws, dv.x * ws + dv.y * wc);
                    }
                    trow[k * 16 + ((n2 + k) & 15)] = dv;   // skewed store
                }
            }
        }
        __syncthreads();
        {
            const float2* trow = T + row * PITCH;
            const int nk = (j == 3) ? 2 : 1;
#pragma unroll
            for (int q = 0; q < 2; q++) {
                if (q >= nk) break;
                const int k1 = (j == 3) ? (3 + q) : j;
                float2 v[16];
#pragma unroll
                for (int t = 0; t < 16; t++)
                    v[t] = trow[k1 * 16 + ((t + k1) & 15)];   // skewed load
                fft16r<U>(v);
#pragma unroll
                for (int k2 = 0; k2 < 16; k2++) X[(k1 + 5 * k2) * PITCH + row] = v[k2];
            }
        }
        __syncthreads();
    }
}

// ---------------- deterministic block reduce (blockDim = NTHR = 10 warps) ----------------
__device__ float blockReduceSum(float v, float* red, int tid) {
#pragma unroll
    for (int o = 16; o > 0; o >>= 1) v += __shfl_down_sync(0xffffffffu, v, o);
    if ((tid & 31) == 0) red[tid >> 5] = v;
    __syncthreads();
    if (tid == 0) {
        float s = 0.f;
        for (int w = 0; w < NTHR / 32; w++) s += red[w];
        red[0] = s;
    }
    __syncthreads();
    float r = red[0];
    __syncthreads();
    return r;
}

#define SMEM_F2 (2 * NPTS * PITCH + 80)
#define SMEM_BYTES (SMEM_F2 * sizeof(float2) + 64 * sizeof(float))

__device__ __forceinline__ void fill_w80(float2* w80, int tid) {
    if (tid < 80) {
        float sv, cv;
        sincospif((float)tid * (1.0f / 40.0f), &sv, &cv);   // 2*pi*tid/80
        w80[tid] = make_float2(cv, sv);
    }
}

// ---------------- kernel 1: Yf = fft2(y), 32 blocks ----------------
__global__ void __launch_bounds__(NTHR, 2) yf_kernel(const float* __restrict__ y) {
    extern __shared__ float sm[];
    float2* A = (float2*)sm;
    float2* B = A + NPTS * PITCH;
    float2* w80 = B + NPTS * PITCH;
    int tid = threadIdx.x;
    int d = blockIdx.x;
    fill_w80(w80, tid);
    for (int idx = tid; idx < IMG; idx += NTHR)
        A[(idx / 80) * PITCH + (idx % 80)] = make_float2(gld(y, (long long)d * IMG + idx, X_FLOATS - 1), 0.f);
    __syncthreads();
    fft2d80<-1>(A, B, w80, tid);
    for (int idx = tid; idx < IMG; idx += NTHR)
        g_Yf[d * IMG + idx] = A[(idx / 80) * PITCH + (idx % 80)];
}

// ---------------- kernel 2: paired loss, 4096 blocks, each handles (pd0, pd0+1) ----------------
// Exploits: TF real -> pack two ifft2s into one complex FFT; psf even + y real ->
// ifft2(psf*Yf) is REAL -> pack two second FFTs too.  2 FFTs per 2 images.
__global__ void __launch_bounds__(NTHR, 2) loss_kernel(const float* __restrict__ tf, const float* __restrict__ y) {
    extern __shared__ float sm[];
    float2* X = (float2*)sm;
    float2* Y = X + NPTS * PITCH;
    float2* w80 = Y + NPTS * PITCH;
    float* red = (float*)(w80 + 80);
    int tid = threadIdx.x;
    int pd0 = 2 * blockIdx.x;
    int pd1 = pd0 + 1;
    int d0 = pd0 & 31, d1 = pd1 & 31;
    fill_w80(w80, tid);
    long long b0 = (long long)pd0 * IMG;
    long long b1 = (long long)pd1 * IMG;
    for (int idx = tid; idx < IMG; idx += NTHR)
        X[(idx / 80) * PITCH + (idx % 80)] =
            make_float2(gld(tf, b0 + idx, TF_TOTAL - 1), gld(tf, b1 + idx, TF_TOTAL - 1));
    __syncthreads();
    fft2d80<1>(X, Y, w80, tid);          // Z = G1 + i*G2 (unscaled; scaling cancels in normalization)

    // phase A: psf magnitudes (m1,m2) into Y; accumulate sums
    float s1 = 0.f, s2 = 0.f;
    for (int idx = tid; idx < IMG; idx += NTHR) {
        int i = idx / 80, j = idx % 80;
        int ni = (i == 0) ? 0 : 80 - i;
        int nj = (j == 0) ? 0 : 80 - j;
        float2 Zk = X[i * PITCH + j];
        float2 Zm = X[ni * PITCH + nj];
        float g1r = 0.5f * (Zk.x + Zm.x), g1i = 0.5f * (Zk.y - Zm.y);
        float g2r = 0.5f * (Zk.y + Zm.y), g2i = 0.5f * (Zm.x - Zk.x);
        float m1 = sqrtf(g1r * g1r + g1i * g1i);
        float m2 = sqrtf(g2r * g2r + g2i * g2i);
        Y[i * PITCH + j] = make_float2(m1, m2);
        s1 += m1; s2 += m2;
    }
    float S1 = blockReduceSum(s1, red, tid);
    float S2 = blockReduceSum(s2, red, tid);
    float invS1 = 1.0f / S1, invS2 = 1.0f / S2;

    // phase B: X(idx) = psf1n(s(idx))*Yf_d0(idx) + i * psf2n(s(idx))*Yf_d1(idx)
    const float2* yf0 = g_Yf + d0 * IMG;
    const float2* yf1 = g_Yf + d1 * IMG;
    for (int idx = tid; idx < IMG; idx += NTHR) {
        int i = idx / 80, j = idx % 80;
        int si = (i >= 40) ? i - 40 : i + 40;
        int sj = (j >= 40) ? j - 40 : j + 40;
        float2 mm = Y[si * PITCH + sj];
        float A = mm.x * invS1, Bc = mm.y * invS2;
        float2 f0 = yf0[idx], f1 = yf1[idx];
        X[i * PITCH + j] = make_float2(A * f0.x - Bc * f1.y, A * f0.y + Bc * f1.x);
    }
    __syncthreads();
    fft2d80<1>(X, Y, w80, tid);          // = r1 + i*r2, both REAL (Hermitian inputs)

    // phase C: losses for both images
    float a0 = 0.f, a1 = 0.f;
    for (int idx = tid; idx < IMG; idx += NTHR) {
        int i = idx / 80, j = idx % 80;
        int si = (i >= 40) ? i - 40 : i + 40;
        int sj = (j >= 40) ? j - 40 : j + 40;
        float2 v = X[si * PITCH + sj];
        float yh0 = fabsf(v.x) * (1.0f / 6400.0f);
        float yh1 = fabsf(v.y) * (1.0f / 6400.0f);
        float df0 = gld(y, (long long)d0 * IMG + idx, X_FLOATS - 1) - yh0;
        float df1 = gld(y, (long long)d1 * IMG + idx, X_FLOATS - 1) - yh1;
        a0 += df0 * df0;
        a1 += df1 * df1;
    }
    float t0 = blockReduceSum(a0, red, tid);
    float t1 = blockReduceSum(a1, red, tid);
    if (tid == 0) {
        g_partial[pd0] = t0;
        g_partial[pd1] = t1;
    }
}

// ---------------- kernel 3: reduce + argmin ----------------
__global__ void argmin_kernel(const float* __restrict__ params, float* __restrict__ out) {
    __shared__ float sl[NPARAMS];
    __shared__ int   si[NPARAMS];
    int tid = threadIdx.x;
    float s = 0.f;
    for (int d = 0; d < NDELAYS; d++) s += g_partial[tid * NDELAYS + d];
    float loss = s / (float)(NDELAYS * IMG);
    sl[tid] = loss; si[tid] = tid;
    __syncthreads();
    for (int st = 128; st > 0; st >>= 1) {
        if (tid < st) {
            float lo = sl[tid + st];
            if (lo < sl[tid] || (lo == sl[tid] && si[tid + st] < si[tid])) {
                sl[tid] = lo; si[tid] = si[tid + st];
            }
        }
        __syncthreads();
    }
    if (tid == 0) {
        g_best = si[0];
        out[X_FLOATS + TF_REAL + 0] = gld(params, (long long)si[0] * 3 + 0, 767);
        out[X_FLOATS + TF_REAL + 1] = gld(params, (long long)si[0] * 3 + 1, 767);
        out[X_FLOATS + TF_REAL + 2] = gld(params, (long long)si[0] * 3 + 2, 767);
        out[X_FLOATS + TF_REAL + 3] = sl[0];
    }
}

// ---------------- kernel 4: copy best TF (real floats) ----------------
__global__ void copytf_kernel(const float* __restrict__ tf, float* __restrict__ out) {
    long long base = (long long)g_best * TF_REAL;
    for (int i = blockIdx.x * blockDim.x + threadIdx.x; i < TF_REAL; i += gridDim.x * blockDim.x)
        out[X_FLOATS + i] = gld(tf, base + i, TF_TOTAL - 1);
}

// ---------------- kernel 5: best_x (Wiener deconv for winner), 32 blocks ----------------
__global__ void __launch_bounds__(NTHR, 2) bestx_kernel(const float* __restrict__ tf, float* __restrict__ out) {
    extern __shared__ float sm[];
    float2* A = (float2*)sm;
    float2* B = A + NPTS * PITCH;
    float2* w80 = B + NPTS * PITCH;
    float* red = (float*)(w80 + 80);
    int tid = threadIdx.x;
    int d = blockIdx.x;
    fill_w80(w80, tid);
    long long base = ((long long)g_best * NDELAYS + d) * IMG;
    for (int idx = tid; idx < IMG; idx += NTHR)
        A[(idx / 80) * PITCH + (idx % 80)] = make_float2(gld(tf, base + idx, TF_TOTAL - 1), 0.f);
    __syncthreads();
    fft2d80<1>(A, B, w80, tid);
    float s = 0.f;
    for (int idx = tid; idx < IMG; idx += NTHR) {
        float2 v = A[(idx / 80) * PITCH + (idx % 80)];
        s += sqrtf(v.x * v.x + v.y * v.y);
    }
    float S = blockReduceSum(s, red, tid);
    float invS = 1.0f / S;
    for (int idx = tid; idx < IMG; idx += NTHR) {
        int i = idx / 80, j = idx % 80;
        int si = (i >= 40) ? i - 40 : i + 40;
        int sj = (j >= 40) ? j - 40 : j + 40;
        float2 a = A[si * PITCH + sj];
        B[i * PITCH + j] = make_float2(sqrtf(a.x * a.x + a.y * a.y) * invS, 0.f);
    }
    __syncthreads();
    fft2d80<-1>(B, A, w80, tid);         // H = fft2(psf)
    const float2* yf = g_Yf + d * IMG;
    for (int idx = tid; idx < IMG; idx += NTHR) {
        int i = idx / 80, j = idx % 80;
        float2 h = B[i * PITCH + j];
        float2 f = yf[idx];
        float den = h.x * h.x + h.y * h.y + LAMBDA;
        B[i * PITCH + j] = make_float2((h.x * f.x + h.y * f.y) / den,
                                       (h.x * f.y - h.y * f.x) / den);
    }
    __syncthreads();
    fft2d80<1>(B, A, w80, tid);
    for (int idx = tid; idx < IMG; idx += NTHR) {
        int i = idx / 80, j = idx % 80;
        int si = (i >= 40) ? i - 40 : i + 40;
        int sj = (j >= 40) ? j - 40 : j + 40;
        float2 v = B[si * PITCH + sj];
        out[d * IMG + idx] = sqrtf(v.x * v.x + v.y * v.y) * (1.0f / 6400.0f);
    }
}

// ---------------- launcher ----------------
extern "C" void kernel_launch(void* const* d_in, const int* in_sizes, int n_in,
                              void* d_out, int out_size) {
    (void)in_sizes; (void)out_size;
    if (n_in < 3 || d_in == nullptr || d_out == nullptr) return;

    const float* y      = (const float*)d_in[0];   // 204800 floats
    const float* tf     = (const float*)d_in[1];   // 52428800 floats (TF real: cos(k(d-w)))
    const float* params = (const float*)d_in[2];   // 768 floats
    float* out = (float*)d_out;                    // 409604 floats: [x | tf | params | loss]

    cudaFuncSetAttribute(yf_kernel,    cudaFuncAttributeMaxDynamicSharedMemorySize, (int)SMEM_BYTES);
    cudaFuncSetAttribute(loss_kernel,  cudaFuncAttributeMaxDynamicSharedMemorySize, (int)SMEM_BYTES);
    cudaFuncSetAttribute(bestx_kernel, cudaFuncAttributeMaxDynamicSharedMemorySize, (int)SMEM_BYTES);

    yf_kernel<<<NDELAYS, NTHR, SMEM_BYTES>>>(y);
    loss_kernel<<<NPARAMS * NDELAYS / 2, NTHR, SMEM_BYTES>>>(tf, y);
    argmin_kernel<<<1, NPARAMS>>>(params, out);
    copytf_kernel<<<256, 256>>>(tf, out);
    bestx_kernel<<<NDELAYS, NTHR, SMEM_BYTES>>>(tf, out);
}

// round 13
// speedup vs baseline: 3.3325x; 1.1287x over previous
#include <cuda_runtime.h>

#define NPTS 80
#define PITCH 84                        // 84 mod 16 == 4 -> conflict-free with 4-thread/row layout
#define NDELAYS 32
#define NPARAMS 256
#define IMG 6400
#define LAMBDA 0.03f
#define X_FLOATS (NDELAYS*IMG)          // 204800 floats for best_x
#define TF_REAL  (NDELAYS*IMG)          // 204800 floats for best tf (real-valued)
#define TF_TOTAL ((long long)NPARAMS * NDELAYS * IMG)   // 52428800 floats
#define NTHR 320                        // 4 threads per row

// ---------------- workspace ----------------
__device__ float2 g_Yf[NDELAYS * IMG];
__device__ float  g_partial[NPARAMS * NDELAYS];
__device__ int    g_best;

__device__ __forceinline__ float gld(const float* p, long long i, long long imax) {
    return (i >= 0 && i <= imax) ? p[i] : 0.f;
}

// ---------------- 16-point FFT in registers (U=+1 inverse, U=-1 forward, unscaled) ----------------
template<int U>
__device__ __forceinline__ void fft16r(float2* v) {
    const float C16[8] = {1.f, 0.9238795325112867f, 0.7071067811865476f, 0.3826834323650898f,
                          0.f, -0.3826834323650898f, -0.7071067811865476f, -0.9238795325112867f};
    const float S16[8] = {0.f, 0.3826834323650898f, 0.7071067811865476f, 0.9238795325112867f,
                          1.f, 0.9238795325112867f, 0.7071067811865476f, 0.3826834323650898f};
    float2 t;
    t = v[1];  v[1]  = v[8];  v[8]  = t;
    t = v[2];  v[2]  = v[4];  v[4]  = t;
    t = v[3];  v[3]  = v[12]; v[12] = t;
    t = v[5];  v[5]  = v[10]; v[10] = t;
    t = v[7];  v[7]  = v[14]; v[14] = t;
    t = v[11]; v[11] = v[13]; v[13] = t;
#pragma unroll
    for (int len = 2; len <= 16; len <<= 1) {
        const int half = len >> 1;
        const int step = 16 / len;
#pragma unroll
        for (int i = 0; i < 16; i += len) {
#pragma unroll
            for (int j = 0; j < half; j++) {
                float wc = C16[j * step];
                float ws = (float)U * S16[j * step];
                float2 a = v[i + j], b = v[i + j + half];
                float tr = b.x * wc - b.y * ws;
                float ti = b.x * ws + b.y * wc;
                v[i + j]        = make_float2(a.x + tr, a.y + ti);
                v[i + j + half] = make_float2(a.x - tr, a.y - ti);
            }
        }
    }
}

// ---------------- 80x80 2D FFT, 4 threads per row (320 threads), in place on X, T scratch ----------------
// Winograd-style radix-5 in stage 1; T uses the k-skewed layout trow[k*16 + ((n2+k)&15)].
template<int U>
__device__ void fft2d80(float2* X, float2* T, const float2* w80, int tid) {
    const float uC2 = 0.5590169943749475f;   // (cos72 - cos144)/2
    const float uS1 = 0.9510565162951535f;   // sin 72
    const float uS2 = 0.5877852522924731f;   // sin 144
    const float u = (float)U;
    const int row = tid >> 2;       // 0..79
    const int j   = tid & 3;        // 0..3
#pragma unroll
    for (int pass = 0; pass < 2; ++pass) {
        // stage 1: radix-5 (Winograd) + W80 twiddle over 4 of the 16 n2-columns
        {
            const float2* s = X + row * PITCH;
            float2* trow = T + row * PITCH;
#pragma unroll
            for (int m = 0; m < 4; m++) {
                const int n2 = j + 4 * m;
                float2 c0 = s[n2], c1 = s[16 + n2], c2 = s[32 + n2], c3 = s[48 + n2], c4 = s[64 + n2];
                float2 p1 = make_float2(c1.x + c4.x, c1.y + c4.y);
                float2 p2 = make_float2(c2.x + c3.x, c2.y + c3.y);
                float2 m3 = make_float2(c1.x - c4.x, c1.y - c4.y);
                float2 m4 = make_float2(c2.x - c3.x, c2.y - c3.y);
                float2 t5 = make_float2(p1.x + p2.x, p1.y + p2.y);
                float2 X0 = make_float2(c0.x + t5.x, c0.y + t5.y);
                float2 aa = make_float2(c0.x - 0.25f * t5.x, c0.y - 0.25f * t5.y);
                float2 bb = make_float2(uC2 * (p1.x - p2.x), uC2 * (p1.y - p2.y));
                float2 Y1 = make_float2(aa.x + bb.x, aa.y + bb.y);
                float2 Y2 = make_float2(aa.x - bb.x, aa.y - bb.y);
                float2 cc = make_float2(uS1 * m3.x + uS2 * m4.x, uS1 * m3.y + uS2 * m4.y);
                float2 dd = make_float2(uS2 * m3.x - uS1 * m4.x, uS2 * m3.y - uS1 * m4.y);
                float2 Xk[5];
                Xk[0] = X0;
                Xk[1] = make_float2(Y1.x - u * cc.y, Y1.y + u * cc.x);
                Xk[4] = make_float2(Y1.x + u * cc.y, Y1.y - u * cc.x);
                Xk[2] = make_float2(Y2.x - u * dd.y, Y2.y + u * dd.x);
                Xk[3] = make_float2(Y2.x + u * dd.y, Y2.y - u * dd.x);
                trow[((n2 + 0) & 15)] = Xk[0];
#pragma unroll
                for (int k = 1; k < 5; k++) {
                    float wc = w80[n2 * k].x, ws = u * w80[n2 * k].y;
                    float2 dv = make_float2(Xk[k].x * wc - Xk[k].y * ws,
                                            Xk[k].x * ws + Xk[k].y * wc);
                    trow[k * 16 + ((n2 + k) & 15)] = dv;   // skewed store
                }
            }
        }
        __syncthreads();
        // stage 2: radix-16 FFTs; j=0,1,2 do k1=j, j=3 does k1=3,4
        {
            const float2* trow = T + row * PITCH;
            const int nk = (j == 3) ? 2 : 1;
#pragma unroll
            for (int q = 0; q < 2; q++) {
                if (q >= nk) break;
                const int k1 = (j == 3) ? (3 + q) : j;
                float2 v[16];
#pragma unroll
                for (int t = 0; t < 16; t++)
                    v[t] = trow[k1 * 16 + ((t + k1) & 15)];   // skewed load
                fft16r<U>(v);
#pragma unroll
                for (int k2 = 0; k2 < 16; k2++) X[(k1 + 5 * k2) * PITCH + row] = v[k2];
            }
        }
        __syncthreads();
    }
}

// ---------------- deterministic block reduces (blockDim = NTHR = 10 warps) ----------------
__device__ float blockReduceSum(float v, float* red, int tid) {
#pragma unroll
    for (int o = 16; o > 0; o >>= 1) v += __shfl_down_sync(0xffffffffu, v, o);
    if ((tid & 31) == 0) red[tid >> 5] = v;
    __syncthreads();
    if (tid == 0) {
        float s = 0.f;
        for (int w = 0; w < NTHR / 32; w++) s += red[w];
        red[0] = s;
    }
    __syncthreads();
    float r = red[0];
    __syncthreads();
    return r;
}

__device__ float2 blockReduceSum2(float2 v, float* red, int tid) {
#pragma unroll
    for (int o = 16; o > 0; o >>= 1) {
        v.x += __shfl_down_sync(0xffffffffu, v.x, o);
        v.y += __shfl_down_sync(0xffffffffu, v.y, o);
    }
    if ((tid & 31) == 0) { red[2 * (tid >> 5)] = v.x; red[2 * (tid >> 5) + 1] = v.y; }
    __syncthreads();
    if (tid == 0) {
        float sx = 0.f, sy = 0.f;
        for (int w = 0; w < NTHR / 32; w++) { sx += red[2 * w]; sy += red[2 * w + 1]; }
        red[0] = sx; red[1] = sy;
    }
    __syncthreads();
    float2 r = make_float2(red[0], red[1]);
    __syncthreads();
    return r;
}

#define SMEM_F2 (2 * NPTS * PITCH + 80)
#define SMEM_BYTES (SMEM_F2 * sizeof(float2) + 64 * sizeof(float))

__device__ __forceinline__ void fill_w80(float2* w80, int tid) {
    if (tid < 80) {
        float sv, cv;
        sincospif((float)tid * (1.0f / 40.0f), &sv, &cv);   // 2*pi*tid/80
        w80[tid] = make_float2(cv, sv);
    }
}

// ---------------- kernel 1: Yf = fft2(y), 32 blocks ----------------
__global__ void __launch_bounds__(NTHR, 2) yf_kernel(const float* __restrict__ y) {
    extern __shared__ float sm[];
    float2* A = (float2*)sm;
    float2* B = A + NPTS * PITCH;
    float2* w80 = B + NPTS * PITCH;
    int tid = threadIdx.x;
    int d = blockIdx.x;
    fill_w80(w80, tid);
    for (int idx = tid; idx < IMG; idx += NTHR)
        A[(idx / 80) * PITCH + (idx % 80)] = make_float2(gld(y, (long long)d * IMG + idx, X_FLOATS - 1), 0.f);
    __syncthreads();
    fft2d80<-1>(A, B, w80, tid);
    for (int idx = tid; idx < IMG; idx += NTHR)
        g_Yf[d * IMG + idx] = A[(idx / 80) * PITCH + (idx % 80)];
}

// ---------------- kernel 2: paired loss, 4096 blocks, each handles (pd0, pd0+1) ----------------
__global__ void __launch_bounds__(NTHR, 2) loss_kernel(const float* __restrict__ tf, const float* __restrict__ y) {
    extern __shared__ float sm[];
    float2* X = (float2*)sm;
    float2* Y = X + NPTS * PITCH;
    float2* w80 = Y + NPTS * PITCH;
    float* red = (float*)(w80 + 80);
    int tid = threadIdx.x;
    int pd0 = 2 * blockIdx.x;
    int pd1 = pd0 + 1;
    int d0 = pd0 & 31, d1 = pd1 & 31;
    fill_w80(w80, tid);
    long long b0 = (long long)pd0 * IMG;
    long long b1 = (long long)pd1 * IMG;
    for (int idx = tid; idx < IMG; idx += NTHR)
        X[(idx / 80) * PITCH + (idx % 80)] =
            make_float2(gld(tf, b0 + idx, TF_TOTAL - 1), gld(tf, b1 + idx, TF_TOTAL - 1));
    __syncthreads();
    fft2d80<1>(X, Y, w80, tid);          // Z = G1 + i*G2 (unscaled; scaling cancels in normalization)

    // phase A: psf magnitudes (m1,m2) into Y, exploiting |G(-k)|=|G(k)| (even field).
    // iterate half-domain i=0..40, write both mirror positions (self-mirrored rows: benign dup writes).
    float2 ss = make_float2(0.f, 0.f);
    for (int idx = tid; idx < 41 * 80; idx += NTHR) {
        int i = idx / 80, j = idx % 80;
        int ni = (i == 0) ? 0 : 80 - i;
        int nj = (j == 0) ? 0 : 80 - j;
        float2 Zk = X[i * PITCH + j];
        float2 Zm = X[ni * PITCH + nj];
        float g1r = 0.5f * (Zk.x + Zm.x), g1i = 0.5f * (Zk.y - Zm.y);
        float g2r = 0.5f * (Zk.y + Zm.y), g2i = 0.5f * (Zm.x - Zk.x);
        float m1 = sqrtf(g1r * g1r + g1i * g1i);
        float m2 = sqrtf(g2r * g2r + g2i * g2i);
        float2 mm = make_float2(m1, m2);
        Y[i * PITCH + j] = mm;
        Y[ni * PITCH + nj] = mm;           // even symmetry
        float wgt = (i >= 1 && i <= 39) ? 2.f : 1.f;
        ss.x += wgt * m1; ss.y += wgt * m2;
    }
    float2 S = blockReduceSum2(ss, red, tid);
    float invS1 = 1.0f / S.x, invS2 = 1.0f / S.y;

    // phase B: X(idx) = psf1n(s(idx))*Yf_d0(idx) + i * psf2n(s(idx))*Yf_d1(idx)
    const float2* yf0 = g_Yf + d0 * IMG;
    const float2* yf1 = g_Yf + d1 * IMG;
    for (int idx = tid; idx < IMG; idx += NTHR) {
        int i = idx / 80, j = idx % 80;
        int si = (i >= 40) ? i - 40 : i + 40;
        int sj = (j >= 40) ? j - 40 : j + 40;
        float2 mm = Y[si * PITCH + sj];
        float A = mm.x * invS1, Bc = mm.y * invS2;
        float2 f0 = yf0[idx], f1 = yf1[idx];
        X[i * PITCH + j] = make_float2(A * f0.x - Bc * f1.y, A * f0.y + Bc * f1.x);
    }
    __syncthreads();
    fft2d80<1>(X, Y, w80, tid);          // = r1 + i*r2, both REAL (Hermitian inputs)

    // phase C: losses for both images
    float2 aa = make_float2(0.f, 0.f);
    for (int idx = tid; idx < IMG; idx += NTHR) {
        int i = idx / 80, j = idx % 80;
        int si = (i >= 40) ? i - 40 : i + 40;
        int sj = (j >= 40) ? j - 40 : j + 40;
        float2 v = X[si * PITCH + sj];
        float yh0 = fabsf(v.x) * (1.0f / 6400.0f);
        float yh1 = fabsf(v.y) * (1.0f / 6400.0f);
        float df0 = gld(y, (long long)d0 * IMG + idx, X_FLOATS - 1) - yh0;
        float df1 = gld(y, (long long)d1 * IMG + idx, X_FLOATS - 1) - yh1;
        aa.x += df0 * df0;
        aa.y += df1 * df1;
    }
    float2 tt = blockReduceSum2(aa, red, tid);
    if (tid == 0) {
        g_partial[pd0] = tt.x;
        g_partial[pd1] = tt.y;
    }
}

// ---------------- kernel 3: reduce + argmin ----------------
__global__ void argmin_kernel(const float* __restrict__ params, float* __restrict__ out) {
    __shared__ float sl[NPARAMS];
    __shared__ int   si[NPARAMS];
    int tid = threadIdx.x;
    float s = 0.f;
    for (int d = 0; d < NDELAYS; d++) s += g_partial[tid * NDELAYS + d];
    float loss = s / (float)(NDELAYS * IMG);
    sl[tid] = loss; si[tid] = tid;
    __syncthreads();
    for (int st = 128; st > 0; st >>= 1) {
        if (tid < st) {
            float lo = sl[tid + st];
            if (lo < sl[tid] || (lo == sl[tid] && si[tid + st] < si[tid])) {
                sl[tid] = lo; si[tid] = si[tid + st];
            }
        }
        __syncthreads();
    }
    if (tid == 0) {
        g_best = si[0];
        out[X_FLOATS + TF_REAL + 0] = gld(params, (long long)si[0] * 3 + 0, 767);
        out[X_FLOATS + TF_REAL + 1] = gld(params, (long long)si[0] * 3 + 1, 767);
        out[X_FLOATS + TF_REAL + 2] = gld(params, (long long)si[0] * 3 + 2, 767);
        out[X_FLOATS + TF_REAL + 3] = sl[0];
    }
}

// ---------------- kernel 4: copy best TF (real floats) ----------------
__global__ void copytf_kernel(const float* __restrict__ tf, float* __restrict__ out) {
    long long base = (long long)g_best * TF_REAL;
    for (int i = blockIdx.x * blockDim.x + threadIdx.x; i < TF_REAL; i += gridDim.x * blockDim.x)
        out[X_FLOATS + i] = gld(tf, base + i, TF_TOTAL - 1);
}

// ---------------- kernel 5: best_x (Wiener deconv for winner), 32 blocks ----------------
__global__ void __launch_bounds__(NTHR, 2) bestx_kernel(const float* __restrict__ tf, float* __restrict__ out) {
    extern __shared__ float sm[];
    float2* A = (float2*)sm;
    float2* B = A + NPTS * PITCH;
    float2* w80 = B + NPTS * PITCH;
    float* red = (float*)(w80 + 80);
    int tid = threadIdx.x;
    int d = blockIdx.x;
    fill_w80(w80, tid);
    long long base = ((long long)g_best * NDELAYS + d) * IMG;
    for (int idx = tid; idx < IMG; idx += NTHR)
        A[(idx / 80) * PITCH + (idx % 80)] = make_float2(gld(tf, base + idx, TF_TOTAL - 1), 0.f);
    __syncthreads();
    fft2d80<1>(A, B, w80, tid);
    float s = 0.f;
    for (int idx = tid; idx < IMG; idx += NTHR) {
        float2 v = A[(idx / 80) * PITCH + (idx % 80)];
        s += sqrtf(v.x * v.x + v.y * v.y);
    }
    float S = blockReduceSum(s, red, tid);
    float invS = 1.0f / S;
    for (int idx = tid; idx < IMG; idx += NTHR) {
        int i = idx / 80, j = idx % 80;
        int si = (i >= 40) ? i - 40 : i + 40;
        int sj = (j >= 40) ? j - 40 : j + 40;
        float2 a = A[si * PITCH + sj];
        B[i * PITCH + j] = make_float2(sqrtf(a.x * a.x + a.y * a.y) * invS, 0.f);
    }
    __syncthreads();
    fft2d80<-1>(B, A, w80, tid);         // H = fft2(psf)
    const float2* yf = g_Yf + d * IMG;
    for (int idx = tid; idx < IMG; idx += NTHR) {
        int i = idx / 80, j = idx % 80;
        float2 h = B[i * PITCH + j];
        float2 f = yf[idx];
        float den = h.x * h.x + h.y * h.y + LAMBDA;
        B[i * PITCH + j] = make_float2((h.x * f.x + h.y * f.y) / den,
                                       (h.x * f.y - h.y * f.x) / den);
    }
    __syncthreads();
    fft2d80<1>(B, A, w80, tid);
    for (int idx = tid; idx < IMG; idx += NTHR) {
        int i = idx / 80, j = idx % 80;
        int si = (i >= 40) ? i - 40 : i + 40;
        int sj = (j >= 40) ? j - 40 : j + 40;
        float2 v = B[si * PITCH + sj];
        out[d * IMG + idx] = sqrtf(v.x * v.x + v.y * v.y) * (1.0f / 6400.0f);
    }
}

// ---------------- launcher ----------------
extern "C" void kernel_launch(void* const* d_in, const int* in_sizes, int n_in,
                              void* d_out, int out_size) {
    (void)in_sizes; (void)out_size;
    if (n_in < 3 || d_in == nullptr || d_out == nullptr) return;

    const float* y      = (const float*)d_in[0];   // 204800 floats
    const float* tf     = (const float*)d_in[1];   // 52428800 floats (TF real: cos(k(d-w)))
    const float* params = (const float*)d_in[2];   // 768 floats
    float* out = (float*)d_out;                    // 409604 floats: [x | tf | params | loss]

    cudaFuncSetAttribute(yf_kernel,    cudaFuncAttributeMaxDynamicSharedMemorySize, (int)SMEM_BYTES);
    cudaFuncSetAttribute(loss_kernel,  cudaFuncAttributeMaxDynamicSharedMemorySize, (int)SMEM_BYTES);
    cudaFuncSetAttribute(bestx_kernel, cudaFuncAttributeMaxDynamicSharedMemorySize, (int)SMEM_BYTES);

    yf_kernel<<<NDELAYS, NTHR, SMEM_BYTES>>>(y);
    loss_kernel<<<NPARAMS * NDELAYS / 2, NTHR, SMEM_BYTES>>>(tf, y);
    argmin_kernel<<<1, NPARAMS>>>(params, out);
    copytf_kernel<<<256, 256>>>(tf, out);
    bestx_kernel<<<NDELAYS, NTHR, SMEM_BYTES>>>(tf, out);
}

// round 14
// speedup vs baseline: 3.6082x; 1.0827x over previous
#include <cuda_runtime.h>

#define NPTS 80
#define PITCH 84                        // 84 mod 16 == 4
#define NDELAYS 32
#define NPARAMS 256
#define IMG 6400
#define LAMBDA 0.03f
#define X_FLOATS (NDELAYS*IMG)          // 204800 floats for best_x
#define TF_REAL  (NDELAYS*IMG)          // 204800 floats for best tf (real-valued)
#define TF_TOTAL ((long long)NPARAMS * NDELAYS * IMG)   // 52428800 floats
#define NTHR 320                        // yf/bestx: 4 threads per row
#define NTHR2 640                       // loss: 8 threads per row

// ---------------- workspace ----------------
__device__ float2 g_Yf[NDELAYS * IMG];
__device__ float  g_partial[NPARAMS * NDELAYS];
__device__ int    g_best;

__device__ __forceinline__ float gld(const float* p, long long i, long long imax) {
    return (i >= 0 && i <= imax) ? p[i] : 0.f;
}
__device__ __forceinline__ int sft(int i) { return (i >= 40) ? i - 40 : i + 40; }

// ---------------- 16-point FFT in registers ----------------
template<int U>
__device__ __forceinline__ void fft16r(float2* v) {
    const float C16[8] = {1.f, 0.9238795325112867f, 0.7071067811865476f, 0.3826834323650898f,
                          0.f, -0.3826834323650898f, -0.7071067811865476f, -0.9238795325112867f};
    const float S16[8] = {0.f, 0.3826834323650898f, 0.7071067811865476f, 0.9238795325112867f,
                          1.f, 0.9238795325112867f, 0.7071067811865476f, 0.3826834323650898f};
    float2 t;
    t = v[1];  v[1]  = v[8];  v[8]  = t;
    t = v[2];  v[2]  = v[4];  v[4]  = t;
    t = v[3];  v[3]  = v[12]; v[12] = t;
    t = v[5];  v[5]  = v[10]; v[10] = t;
    t = v[7];  v[7]  = v[14]; v[14] = t;
    t = v[11]; v[11] = v[13]; v[13] = t;
#pragma unroll
    for (int len = 2; len <= 16; len <<= 1) {
        const int half = len >> 1;
        const int step = 16 / len;
#pragma unroll
        for (int i = 0; i < 16; i += len) {
#pragma unroll
            for (int j = 0; j < half; j++) {
                float wc = C16[j * step];
                float ws = (float)U * S16[j * step];
                float2 a = v[i + j], b = v[i + j + half];
                float tr = b.x * wc - b.y * ws;
                float ti = b.x * ws + b.y * wc;
                v[i + j]        = make_float2(a.x + tr, a.y + ti);
                v[i + j + half] = make_float2(a.x - tr, a.y - ti);
            }
        }
    }
}

// ---------------- Winograd radix-5 + W80 twiddle + skewed store ----------------
template<int U>
__device__ __forceinline__ void radix5_store(const float2 c[5], int n2, const float2* w80, float2* trow) {
    const float uC2 = 0.5590169943749475f;
    const float uS1 = 0.9510565162951535f;
    const float uS2 = 0.5877852522924731f;
    const float u = (float)U;
    float2 p1 = make_float2(c[1].x + c[4].x, c[1].y + c[4].y);
    float2 p2 = make_float2(c[2].x + c[3].x, c[2].y + c[3].y);
    float2 m3 = make_float2(c[1].x - c[4].x, c[1].y - c[4].y);
    float2 m4 = make_float2(c[2].x - c[3].x, c[2].y - c[3].y);
    float2 t5 = make_float2(p1.x + p2.x, p1.y + p2.y);
    float2 aa = make_float2(c[0].x - 0.25f * t5.x, c[0].y - 0.25f * t5.y);
    float2 bb = make_float2(uC2 * (p1.x - p2.x), uC2 * (p1.y - p2.y));
    float2 Y1 = make_float2(aa.x + bb.x, aa.y + bb.y);
    float2 Y2 = make_float2(aa.x - bb.x, aa.y - bb.y);
    float2 cc = make_float2(uS1 * m3.x + uS2 * m4.x, uS1 * m3.y + uS2 * m4.y);
    float2 dd = make_float2(uS2 * m3.x - uS1 * m4.x, uS2 * m3.y - uS1 * m4.y);
    float2 Xk[5];
    Xk[0] = make_float2(c[0].x + t5.x, c[0].y + t5.y);
    Xk[1] = make_float2(Y1.x - u * cc.y, Y1.y + u * cc.x);
    Xk[4] = make_float2(Y1.x + u * cc.y, Y1.y - u * cc.x);
    Xk[2] = make_float2(Y2.x - u * dd.y, Y2.y + u * dd.x);
    Xk[3] = make_float2(Y2.x + u * dd.y, Y2.y - u * dd.x);
    trow[n2] = Xk[0];
#pragma unroll
    for (int k = 1; k < 5; k++) {
        float wc = w80[n2 * k].x, ws = (float)U * w80[n2 * k].y;
        trow[k * 16 + ((n2 + k) & 15)] =
            make_float2(Xk[k].x * wc - Xk[k].y * ws, Xk[k].x * ws + Xk[k].y * wc);
    }
}

// ---------------- 80x80 2D FFT, 4 threads/row (yf/bestx path, 320 threads) ----------------
template<int U>
__device__ void fft2d80(float2* X, float2* T, const float2* w80, int tid) {
    const int row = tid >> 2;
    const int j   = tid & 3;
#pragma unroll
    for (int pass = 0; pass < 2; ++pass) {
        {
            const float2* s = X + row * PITCH;
            float2* trow = T + row * PITCH;
#pragma unroll
            for (int m = 0; m < 4; m++) {
                const int n2 = j + 4 * m;
                float2 c[5];
#pragma unroll
                for (int n1 = 0; n1 < 5; n1++) c[n1] = s[16 * n1 + n2];
                radix5_store<U>(c, n2, w80, trow);
            }
        }
        __syncthreads();
        {
            const float2* trow = T + row * PITCH;
            const int nk = (j == 3) ? 2 : 1;
#pragma unroll
            for (int q = 0; q < 2; q++) {
                if (q >= nk) break;
                const int k1 = (j == 3) ? (3 + q) : j;
                float2 v[16];
#pragma unroll
                for (int t = 0; t < 16; t++)
                    v[t] = trow[k1 * 16 + ((t + k1) & 15)];
                fft16r<U>(v);
#pragma unroll
                for (int k2 = 0; k2 < 16; k2++) X[(k1 + 5 * k2) * PITCH + row] = v[k2];
            }
        }
        __syncthreads();
    }
}

// ---------------- block reduces ----------------
__device__ float blockReduceSum(float v, float* red, int tid) {
#pragma unroll
    for (int o = 16; o > 0; o >>= 1) v += __shfl_down_sync(0xffffffffu, v, o);
    if ((tid & 31) == 0) red[tid >> 5] = v;
    __syncthreads();
    if (tid == 0) {
        float s = 0.f;
        for (int w = 0; w < (int)(blockDim.x >> 5); w++) s += red[w];
        red[0] = s;
    }
    __syncthreads();
    float r = red[0];
    __syncthreads();
    return r;
}

__device__ float2 blockReduceSum2(float2 v, float* red, int tid) {
#pragma unroll
    for (int o = 16; o > 0; o >>= 1) {
        v.x += __shfl_down_sync(0xffffffffu, v.x, o);
        v.y += __shfl_down_sync(0xffffffffu, v.y, o);
    }
    if ((tid & 31) == 0) { red[2 * (tid >> 5)] = v.x; red[2 * (tid >> 5) + 1] = v.y; }
    __syncthreads();
    if (tid == 0) {
        float sx = 0.f, sy = 0.f;
        for (int w = 0; w < (int)(blockDim.x >> 5); w++) { sx += red[2 * w]; sy += red[2 * w + 1]; }
        red[0] = sx; red[1] = sy;
    }
    __syncthreads();
    float2 r = make_float2(red[0], red[1]);
    __syncthreads();
    return r;
}

#define SMEM_F2 (2 * NPTS * PITCH + 80)
#define SMEM_BYTES (SMEM_F2 * sizeof(float2) + 64 * sizeof(float))

__device__ __forceinline__ void fill_w80(float2* w80, int tid) {
    if (tid < 80) {
        float sv, cv;
        sincospif((float)tid * (1.0f / 40.0f), &sv, &cv);
        w80[tid] = make_float2(cv, sv);
    }
}

// ---------------- kernel 1: Yf = fft2(y), 32 blocks ----------------
__global__ void __launch_bounds__(NTHR, 2) yf_kernel(const float* __restrict__ y) {
    extern __shared__ float sm[];
    float2* A = (float2*)sm;
    float2* B = A + NPTS * PITCH;
    float2* w80 = B + NPTS * PITCH;
    int tid = threadIdx.x;
    int d = blockIdx.x;
    fill_w80(w80, tid);
    for (int idx = tid; idx < IMG; idx += NTHR)
        A[(idx / 80) * PITCH + (idx % 80)] = make_float2(gld(y, (long long)d * IMG + idx, X_FLOATS - 1), 0.f);
    __syncthreads();
    fft2d80<-1>(A, B, w80, tid);
    for (int idx = tid; idx < IMG; idx += NTHR)
        g_Yf[d * IMG + idx] = A[(idx / 80) * PITCH + (idx % 80)];
}

// ---------------- kernel 2: paired loss, 4096 blocks, 640 threads (8/row), fused phases ----------------
__global__ void __launch_bounds__(NTHR2, 2) loss_kernel(const float* __restrict__ tf, const float* __restrict__ y) {
    extern __shared__ float sm[];
    float2* X = (float2*)sm;
    float2* Y = X + NPTS * PITCH;
    float2* w80 = Y + NPTS * PITCH;
    float* red = (float*)(w80 + 80);
    const int tid = threadIdx.x;
    const int row = tid >> 3;       // 0..79
    const int j   = tid & 7;        // 0..7
    const int pd0 = 2 * blockIdx.x;
    const int pd1 = pd0 + 1;
    const int d0 = pd0 & 31, d1 = pd1 & 31;
    fill_w80(w80, tid);
    __syncthreads();
    const long long b0 = (long long)pd0 * IMG + row * 80;
    const long long b1 = (long long)pd1 * IMG + row * 80;

    // ---- FFT1 pass 0, stage 1: read TF directly from global (fused load) ----
    {
        float2* trow = Y + row * PITCH;
#pragma unroll
        for (int m = 0; m < 2; m++) {
            const int n2 = j + 8 * m;
            float2 c[5];
#pragma unroll
            for (int n1 = 0; n1 < 5; n1++) {
                int col = 16 * n1 + n2;
                c[n1] = make_float2(tf[b0 + col], tf[b1 + col]);
            }
            radix5_store<1>(c, n2, w80, trow);
        }
    }
    __syncthreads();
    // ---- FFT1 pass 0, stage 2: Y(skew) -> X (transposed) ----
    if (j < 5) {
        const float2* trow = Y + row * PITCH;
        const int k1 = j;
        float2 v[16];
#pragma unroll
        for (int t = 0; t < 16; t++) v[t] = trow[k1 * 16 + ((t + k1) & 15)];
        fft16r<1>(v);
#pragma unroll
        for (int k2 = 0; k2 < 16; k2++) X[(k1 + 5 * k2) * PITCH + row] = v[k2];
    }
    __syncthreads();
    // ---- FFT1 pass 1, stage 1: X -> Y(skew) ----
    {
        const float2* s = X + row * PITCH;
        float2* trow = Y + row * PITCH;
#pragma unroll
        for (int m = 0; m < 2; m++) {
            const int n2 = j + 8 * m;
            float2 c[5];
#pragma unroll
            for (int n1 = 0; n1 < 5; n1++) c[n1] = s[16 * n1 + n2];
            radix5_store<1>(c, n2, w80, trow);
        }
    }
    __syncthreads();
    // ---- FFT1 pass 1, stage 2: Y(skew) -> X ----
    if (j < 5) {
        const float2* trow = Y + row * PITCH;
        const int k1 = j;
        float2 v[16];
#pragma unroll
        for (int t = 0; t < 16; t++) v[t] = trow[k1 * 16 + ((t + k1) & 15)];
        fft16r<1>(v);
#pragma unroll
        for (int k2 = 0; k2 < 16; k2++) X[(k1 + 5 * k2) * PITCH + row] = v[k2];
    }
    __syncthreads();

    // ---- phase A: psf magnitudes (half-domain, even symmetry) X -> Y; sums ----
    float2 ss = make_float2(0.f, 0.f);
    for (int idx = tid; idx < 41 * 80; idx += NTHR2) {
        int i = idx / 80, jc = idx % 80;
        int ni = (i == 0) ? 0 : 80 - i;
        int nj = (jc == 0) ? 0 : 80 - jc;
        float2 Zk = X[i * PITCH + jc];
        float2 Zm = X[ni * PITCH + nj];
        float g1r = 0.5f * (Zk.x + Zm.x), g1i = 0.5f * (Zk.y - Zm.y);
        float g2r = 0.5f * (Zk.y + Zm.y), g2i = 0.5f * (Zm.x - Zk.x);
        float m1 = sqrtf(g1r * g1r + g1i * g1i);
        float m2 = sqrtf(g2r * g2r + g2i * g2i);
        float2 mm = make_float2(m1, m2);
        Y[i * PITCH + jc] = mm;
        Y[ni * PITCH + nj] = mm;
        float wgt = (i >= 1 && i <= 39) ? 2.f : 1.f;
        ss.x += wgt * m1; ss.y += wgt * m2;
    }
    float2 S = blockReduceSum2(ss, red, tid);
    const float invS1 = 1.0f / S.x, invS2 = 1.0f / S.y;

    // ---- FFT2 pass 0, stage 1: product (Y shifted * g_Yf) computed on the fly -> X(skew) ----
    const float2* yf0 = g_Yf + d0 * IMG + row * 80;
    const float2* yf1 = g_Yf + d1 * IMG + row * 80;
    {
        const float2* ysh = Y + sft(row) * PITCH;
        float2* trow = X + row * PITCH;
#pragma unroll
        for (int m = 0; m < 2; m++) {
            const int n2 = j + 8 * m;
            float2 c[5];
#pragma unroll
            for (int n1 = 0; n1 < 5; n1++) {
                int col = 16 * n1 + n2;
                float2 mm = ysh[sft(col)];
                float A = mm.x * invS1, Bc = mm.y * invS2;
                float2 f0 = yf0[col], f1 = yf1[col];
                c[n1] = make_float2(A * f0.x - Bc * f1.y, A * f0.y + Bc * f1.x);
            }
            radix5_store<1>(c, n2, w80, trow);
        }
    }
    __syncthreads();
    // ---- FFT2 pass 0, stage 2: X(skew) -> Y ----
    if (j < 5) {
        const float2* trow = X + row * PITCH;
        const int k1 = j;
        float2 v[16];
#pragma unroll
        for (int t = 0; t < 16; t++) v[t] = trow[k1 * 16 + ((t + k1) & 15)];
        fft16r<1>(v);
#pragma unroll
        for (int k2 = 0; k2 < 16; k2++) Y[(k1 + 5 * k2) * PITCH + row] = v[k2];
    }
    __syncthreads();
    // ---- FFT2 pass 1, stage 1: Y -> X(skew) ----
    {
        const float2* s = Y + row * PITCH;
        float2* trow = X + row * PITCH;
#pragma unroll
        for (int m = 0; m < 2; m++) {
            const int n2 = j + 8 * m;
            float2 c[5];
#pragma unroll
            for (int n1 = 0; n1 < 5; n1++) c[n1] = s[16 * n1 + n2];
            radix5_store<1>(c, n2, w80, trow);
        }
    }
    __syncthreads();
    // ---- FFT2 pass 1, stage 2 fused with loss: no store ----
    float2 aa = make_float2(0.f, 0.f);
    if (j < 5) {
        const float2* trow = X + row * PITCH;
        const int k1 = j;
        float2 v[16];
#pragma unroll
        for (int t = 0; t < 16; t++) v[t] = trow[k1 * 16 + ((t + k1) & 15)];
        fft16r<1>(v);
        const int yj = sft(row);
        const float* y0 = y + d0 * IMG;
        const float* y1 = y + d1 * IMG;
#pragma unroll
        for (int k2 = 0; k2 < 16; k2++) {
            int iF = k1 + 5 * k2;
            int yi = sft(iF);
            float yv0 = y0[yi * 80 + yj];
            float yv1 = y1[yi * 80 + yj];
            float df0 = yv0 - fabsf(v[k2].x) * (1.0f / 6400.0f);
            float df1 = yv1 - fabsf(v[k2].y) * (1.0f / 6400.0f);
            aa.x += df0 * df0;
            aa.y += df1 * df1;
        }
    }
    float2 tt = blockReduceSum2(aa, red, tid);
    if (tid == 0) {
        g_partial[pd0] = tt.x;
        g_partial[pd1] = tt.y;
    }
}

// ---------------- kernel 3: reduce + argmin ----------------
__global__ void argmin_kernel(const float* __restrict__ params, float* __restrict__ out) {
    __shared__ float sl[NPARAMS];
    __shared__ int   si[NPARAMS];
    int tid = threadIdx.x;
    float s = 0.f;
    for (int d = 0; d < NDELAYS; d++) s += g_partial[tid * NDELAYS + d];
    float loss = s / (float)(NDELAYS * IMG);
    sl[tid] = loss; si[tid] = tid;
    __syncthreads();
    for (int st = 128; st > 0; st >>= 1) {
        if (tid < st) {
            float lo = sl[tid + st];
            if (lo < sl[tid] || (lo == sl[tid] && si[tid + st] < si[tid])) {
                sl[tid] = lo; si[tid] = si[tid + st];
            }
        }
        __syncthreads();
    }
    if (tid == 0) {
        g_best = si[0];
        out[X_FLOATS + TF_REAL + 0] = gld(params, (long long)si[0] * 3 + 0, 767);
        out[X_FLOATS + TF_REAL + 1] = gld(params, (long long)si[0] * 3 + 1, 767);
        out[X_FLOATS + TF_REAL + 2] = gld(params, (long long)si[0] * 3 + 2, 767);
        out[X_FLOATS + TF_REAL + 3] = sl[0];
    }
}

// ---------------- kernel 4: copy best TF (real floats) ----------------
__global__ void copytf_kernel(const float* __restrict__ tf, float* __restrict__ out) {
    long long base = (long long)g_best * TF_REAL;
    for (int i = blockIdx.x * blockDim.x + threadIdx.x; i < TF_REAL; i += gridDim.x * blockDim.x)
        out[X_FLOATS + i] = gld(tf, base + i, TF_TOTAL - 1);
}

// ---------------- kernel 5: best_x (Wiener deconv for winner), 32 blocks ----------------
__global__ void __launch_bounds__(NTHR, 2) bestx_kernel(const float* __restrict__ tf, float* __restrict__ out) {
    extern __shared__ float sm[];
    float2* A = (float2*)sm;
    float2* B = A + NPTS * PITCH;
    float2* w80 = B + NPTS * PITCH;
    float* red = (float*)(w80 + 80);
    int tid = threadIdx.x;
    int d = blockIdx.x;
    fill_w80(w80, tid);
    long long base = ((long long)g_best * NDELAYS + d) * IMG;
    for (int idx = tid; idx < IMG; idx += NTHR)
        A[(idx / 80) * PITCH + (idx % 80)] = make_float2(gld(tf, base + idx, TF_TOTAL - 1), 0.f);
    __syncthreads();
    fft2d80<1>(A, B, w80, tid);
    float s = 0.f;
    for (int idx = tid; idx < IMG; idx += NTHR) {
        float2 v = A[(idx / 80) * PITCH + (idx % 80)];
        s += sqrtf(v.x * v.x + v.y * v.y);
    }
    float S = blockReduceSum(s, red, tid);
    float invS = 1.0f / S;
    for (int idx = tid; idx < IMG; idx += NTHR) {
        int i = idx / 80, j = idx % 80;
        int si = sft(i), sj = sft(j);
        float2 a = A[si * PITCH + sj];
        B[i * PITCH + j] = make_float2(sqrtf(a.x * a.x + a.y * a.y) * invS, 0.f);
    }
    __syncthreads();
    fft2d80<-1>(B, A, w80, tid);         // H = fft2(psf)
    const float2* yf = g_Yf + d * IMG;
    for (int idx = tid; idx < IMG; idx += NTHR) {
        int i = idx / 80, j = idx % 80;
        float2 h = B[i * PITCH + j];
        float2 f = yf[idx];
        float den = h.x * h.x + h.y * h.y + LAMBDA;
        B[i * PITCH + j] = make_float2((h.x * f.x + h.y * f.y) / den,
                                       (h.x * f.y - h.y * f.x) / den);
    }
    __syncthreads();
    fft2d80<1>(B, A, w80, tid);
    for (int idx = tid; idx < IMG; idx += NTHR) {
        int i = idx / 80, j = idx % 80;
        int si = sft(i), sj = sft(j);
        float2 v = B[si * PITCH + sj];
        out[d * IMG + idx] = sqrtf(v.x * v.x + v.y * v.y) * (1.0f / 6400.0f);
    }
}

// ---------------- launcher ----------------
extern "C" void kernel_launch(void* const* d_in, const int* in_sizes, int n_in,
                              void* d_out, int out_size) {
    (void)in_sizes; (void)out_size;
    if (n_in < 3 || d_in == nullptr || d_out == nullptr) return;

    const float* y      = (const float*)d_in[0];   // 204800 floats
    const float* tf     = (const float*)d_in[1];   // 52428800 floats (TF real: cos(k(d-w)))
    const float* params = (const float*)d_in[2];   // 768 floats
    float* out = (float*)d_out;                    // 409604 floats: [x | tf | params | loss]

    cudaFuncSetAttribute(yf_kernel,    cudaFuncAttributeMaxDynamicSharedMemorySize, (int)SMEM_BYTES);
    cudaFuncSetAttribute(loss_kernel,  cudaFuncAttributeMaxDynamicSharedMemorySize, (int)SMEM_BYTES);
    cudaFuncSetAttribute(bestx_kernel, cudaFuncAttributeMaxDynamicSharedMemorySize, (int)SMEM_BYTES);

    yf_kernel<<<NDELAYS, NTHR, SMEM_BYTES>>>(y);
    loss_kernel<<<NPARAMS * NDELAYS / 2, NTHR2, SMEM_BYTES>>>(tf, y);
    argmin_kernel<<<1, NPARAMS>>>(params, out);
    copytf_kernel<<<256, 256>>>(tf, out);
    bestx_kernel<<<NDELAYS, NTHR, SMEM_BYTES>>>(tf, out);
}

// round 15
// speedup vs baseline: 4.0020x; 1.1092x over previous
#include <cuda_runtime.h>

#define NPTS 80
#define PITCH 88                        // 88 mod 16 == 8 -> conflict-free with 8-thread/row layout
#define NDELAYS 32
#define NPARAMS 256
#define IMG 6400
#define LAMBDA 0.03f
#define X_FLOATS (NDELAYS*IMG)          // 204800 floats for best_x
#define TF_REAL  (NDELAYS*IMG)          // 204800 floats for best tf (real-valued)
#define TF_TOTAL ((long long)NPARAMS * NDELAYS * IMG)   // 52428800 floats
#define NTHR2 640                       // 8 threads per row

// ---------------- workspace ----------------
__device__ float2 g_Yf[NDELAYS * IMG];
__device__ float  g_partial[NPARAMS * NDELAYS];
__device__ int    g_best;

__device__ __forceinline__ float gld(const float* p, long long i, long long imax) {
    return (i >= 0 && i <= imax) ? p[i] : 0.f;
}
__device__ __forceinline__ int sft(int i) { return (i >= 40) ? i - 40 : i + 40; }

// ---------------- 16-point FFT in registers ----------------
template<int U>
__device__ __forceinline__ void fft16r(float2* v) {
    const float C16[8] = {1.f, 0.9238795325112867f, 0.7071067811865476f, 0.3826834323650898f,
                          0.f, -0.3826834323650898f, -0.7071067811865476f, -0.9238795325112867f};
    const float S16[8] = {0.f, 0.3826834323650898f, 0.7071067811865476f, 0.9238795325112867f,
                          1.f, 0.9238795325112867f, 0.7071067811865476f, 0.3826834323650898f};
    float2 t;
    t = v[1];  v[1]  = v[8];  v[8]  = t;
    t = v[2];  v[2]  = v[4];  v[4]  = t;
    t = v[3];  v[3]  = v[12]; v[12] = t;
    t = v[5];  v[5]  = v[10]; v[10] = t;
    t = v[7];  v[7]  = v[14]; v[14] = t;
    t = v[11]; v[11] = v[13]; v[13] = t;
#pragma unroll
    for (int len = 2; len <= 16; len <<= 1) {
        const int half = len >> 1;
        const int step = 16 / len;
#pragma unroll
        for (int i = 0; i < 16; i += len) {
#pragma unroll
            for (int j = 0; j < half; j++) {
                float wc = C16[j * step];
                float ws = (float)U * S16[j * step];
                float2 a = v[i + j], b = v[i + j + half];
                float tr = b.x * wc - b.y * ws;
                float ti = b.x * ws + b.y * wc;
                v[i + j]        = make_float2(a.x + tr, a.y + ti);
                v[i + j + half] = make_float2(a.x - tr, a.y - ti);
            }
        }
    }
}

// ---------------- Winograd radix-5 + W80 twiddle + skewed store ----------------
template<int U>
__device__ __forceinline__ void radix5_store(const float2 c[5], int n2, const float2* w80, float2* trow) {
    const float uC2 = 0.5590169943749475f;
    const float uS1 = 0.9510565162951535f;
    const float uS2 = 0.5877852522924731f;
    const float u = (float)U;
    float2 p1 = make_float2(c[1].x + c[4].x, c[1].y + c[4].y);
    float2 p2 = make_float2(c[2].x + c[3].x, c[2].y + c[3].y);
    float2 m3 = make_float2(c[1].x - c[4].x, c[1].y - c[4].y);
    float2 m4 = make_float2(c[2].x - c[3].x, c[2].y - c[3].y);
    float2 t5 = make_float2(p1.x + p2.x, p1.y + p2.y);
    float2 aa = make_float2(c[0].x - 0.25f * t5.x, c[0].y - 0.25f * t5.y);
    float2 bb = make_float2(uC2 * (p1.x - p2.x), uC2 * (p1.y - p2.y));
    float2 Y1 = make_float2(aa.x + bb.x, aa.y + bb.y);
    float2 Y2 = make_float2(aa.x - bb.x, aa.y - bb.y);
    float2 cc = make_float2(uS1 * m3.x + uS2 * m4.x, uS1 * m3.y + uS2 * m4.y);
    float2 dd = make_float2(uS2 * m3.x - uS1 * m4.x, uS2 * m3.y - uS1 * m4.y);
    float2 Xk[5];
    Xk[0] = make_float2(c[0].x + t5.x, c[0].y + t5.y);
    Xk[1] = make_float2(Y1.x - u * cc.y, Y1.y + u * cc.x);
    Xk[4] = make_float2(Y1.x + u * cc.y, Y1.y - u * cc.x);
    Xk[2] = make_float2(Y2.x - u * dd.y, Y2.y + u * dd.x);
    Xk[3] = make_float2(Y2.x + u * dd.y, Y2.y - u * dd.x);
    trow[n2] = Xk[0];
#pragma unroll
    for (int k = 1; k < 5; k++) {
        float wc = w80[n2 * k].x, ws = (float)U * w80[n2 * k].y;
        trow[k * 16 + ((n2 + k) & 15)] =
            make_float2(Xk[k].x * wc - Xk[k].y * ws, Xk[k].x * ws + Xk[k].y * wc);
    }
}

// ---------------- 80x80 2D FFT, 8 threads/row (640 threads), in place on X, T scratch ----------------
template<int U>
__device__ void fft2d80_8(float2* X, float2* T, const float2* w80, int row, int j) {
#pragma unroll
    for (int pass = 0; pass < 2; ++pass) {
        {
            const float2* s = X + row * PITCH;
            float2* trow = T + row * PITCH;
#pragma unroll
            for (int m = 0; m < 2; m++) {
                const int n2 = j + 8 * m;
                float2 c[5];
#pragma unroll
                for (int n1 = 0; n1 < 5; n1++) c[n1] = s[16 * n1 + n2];
                radix5_store<U>(c, n2, w80, trow);
            }
        }
        __syncthreads();
        if (j < 5) {
            const float2* trow = T + row * PITCH;
            const int k1 = j;
            float2 v[16];
#pragma unroll
            for (int t = 0; t < 16; t++) v[t] = trow[k1 * 16 + ((t + k1) & 15)];
            fft16r<U>(v);
#pragma unroll
            for (int k2 = 0; k2 < 16; k2++) X[(k1 + 5 * k2) * PITCH + row] = v[k2];
        }
        __syncthreads();
    }
}

// ---------------- block reduces ----------------
__device__ float blockReduceSum(float v, float* red, int tid) {
#pragma unroll
    for (int o = 16; o > 0; o >>= 1) v += __shfl_down_sync(0xffffffffu, v, o);
    if ((tid & 31) == 0) red[tid >> 5] = v;
    __syncthreads();
    if (tid == 0) {
        float s = 0.f;
        for (int w = 0; w < (int)(blockDim.x >> 5); w++) s += red[w];
        red[0] = s;
    }
    __syncthreads();
    float r = red[0];
    __syncthreads();
    return r;
}

__device__ float2 blockReduceSum2(float2 v, float* red, int tid) {
#pragma unroll
    for (int o = 16; o > 0; o >>= 1) {
        v.x += __shfl_down_sync(0xffffffffu, v.x, o);
        v.y += __shfl_down_sync(0xffffffffu, v.y, o);
    }
    if ((tid & 31) == 0) { red[2 * (tid >> 5)] = v.x; red[2 * (tid >> 5) + 1] = v.y; }
    __syncthreads();
    if (tid == 0) {
        float sx = 0.f, sy = 0.f;
        for (int w = 0; w < (int)(blockDim.x >> 5); w++) { sx += red[2 * w]; sy += red[2 * w + 1]; }
        red[0] = sx; red[1] = sy;
    }
    __syncthreads();
    float2 r = make_float2(red[0], red[1]);
    __syncthreads();
    return r;
}

#define SMEM_F2 (2 * NPTS * PITCH + 80)
#define SMEM_BYTES (SMEM_F2 * sizeof(float2) + 64 * sizeof(float))

__device__ __forceinline__ void fill_w80(float2* w80, int tid) {
    if (tid < 80) {
        float sv, cv;
        sincospif((float)tid * (1.0f / 40.0f), &sv, &cv);
        w80[tid] = make_float2(cv, sv);
    }
}

// ---------------- kernel 1: Yf = fft2(y), 32 blocks, 640 threads ----------------
__global__ void __launch_bounds__(NTHR2, 2) yf_kernel(const float* __restrict__ y) {
    extern __shared__ float sm[];
    float2* A = (float2*)sm;
    float2* B = A + NPTS * PITCH;
    float2* w80 = B + NPTS * PITCH;
    int tid = threadIdx.x;
    int d = blockIdx.x;
    fill_w80(w80, tid);
    for (int idx = tid; idx < IMG; idx += NTHR2)
        A[(idx / 80) * PITCH + (idx % 80)] = make_float2(gld(y, (long long)d * IMG + idx, X_FLOATS - 1), 0.f);
    __syncthreads();
    fft2d80_8<-1>(A, B, w80, tid >> 3, tid & 7);
    for (int idx = tid; idx < IMG; idx += NTHR2)
        g_Yf[d * IMG + idx] = A[(idx / 80) * PITCH + (idx % 80)];
}

// ---------------- kernel 2: paired loss, 4096 blocks, 640 threads (8/row), fused phases ----------------
__global__ void __launch_bounds__(NTHR2, 2) loss_kernel(const float* __restrict__ tf, const float* __restrict__ y) {
    extern __shared__ float sm[];
    float2* X = (float2*)sm;
    float2* Y = X + NPTS * PITCH;
    float2* w80 = Y + NPTS * PITCH;
    float* red = (float*)(w80 + 80);
    const int tid = threadIdx.x;
    const int row = tid >> 3;       // 0..79
    const int j   = tid & 7;        // 0..7
    const int pd0 = 2 * blockIdx.x;
    const int pd1 = pd0 + 1;
    const int d0 = pd0 & 31, d1 = pd1 & 31;
    fill_w80(w80, tid);
    __syncthreads();
    const long long b0 = (long long)pd0 * IMG + row * 80;
    const long long b1 = (long long)pd1 * IMG + row * 80;

    // ---- FFT1 pass 0, stage 1: read TF directly from global ----
    {
        float2* trow = Y + row * PITCH;
#pragma unroll
        for (int m = 0; m < 2; m++) {
            const int n2 = j + 8 * m;
            float2 c[5];
#pragma unroll
            for (int n1 = 0; n1 < 5; n1++) {
                int col = 16 * n1 + n2;
                c[n1] = make_float2(tf[b0 + col], tf[b1 + col]);
            }
            radix5_store<1>(c, n2, w80, trow);
        }
    }
    __syncthreads();
    // ---- FFT1 pass 0, stage 2 ----
    if (j < 5) {
        const float2* trow = Y + row * PITCH;
        const int k1 = j;
        float2 v[16];
#pragma unroll
        for (int t = 0; t < 16; t++) v[t] = trow[k1 * 16 + ((t + k1) & 15)];
        fft16r<1>(v);
#pragma unroll
        for (int k2 = 0; k2 < 16; k2++) X[(k1 + 5 * k2) * PITCH + row] = v[k2];
    }
    __syncthreads();
    // ---- FFT1 pass 1, stage 1 ----
    {
        const float2* s = X + row * PITCH;
        float2* trow = Y + row * PITCH;
#pragma unroll
        for (int m = 0; m < 2; m++) {
            const int n2 = j + 8 * m;
            float2 c[5];
#pragma unroll
            for (int n1 = 0; n1 < 5; n1++) c[n1] = s[16 * n1 + n2];
            radix5_store<1>(c, n2, w80, trow);
        }
    }
    __syncthreads();
    // ---- FFT1 pass 1, stage 2 ----
    if (j < 5) {
        const float2* trow = Y + row * PITCH;
        const int k1 = j;
        float2 v[16];
#pragma unroll
        for (int t = 0; t < 16; t++) v[t] = trow[k1 * 16 + ((t + k1) & 15)];
        fft16r<1>(v);
#pragma unroll
        for (int k2 = 0; k2 < 16; k2++) X[(k1 + 5 * k2) * PITCH + row] = v[k2];
    }
    __syncthreads();

    // ---- phase A: psf magnitudes (half-domain, even symmetry) X -> Y; sums ----
    float2 ss = make_float2(0.f, 0.f);
    for (int idx = tid; idx < 41 * 80; idx += NTHR2) {
        int i = idx / 80, jc = idx % 80;
        int ni = (i == 0) ? 0 : 80 - i;
        int nj = (jc == 0) ? 0 : 80 - jc;
        float2 Zk = X[i * PITCH + jc];
        float2 Zm = X[ni * PITCH + nj];
        float g1r = 0.5f * (Zk.x + Zm.x), g1i = 0.5f * (Zk.y - Zm.y);
        float g2r = 0.5f * (Zk.y + Zm.y), g2i = 0.5f * (Zm.x - Zk.x);
        float m1 = sqrtf(g1r * g1r + g1i * g1i);
        float m2 = sqrtf(g2r * g2r + g2i * g2i);
        float2 mm = make_float2(m1, m2);
        Y[i * PITCH + jc] = mm;
        Y[ni * PITCH + nj] = mm;
        float wgt = (i >= 1 && i <= 39) ? 2.f : 1.f;
        ss.x += wgt * m1; ss.y += wgt * m2;
    }
    float2 S = blockReduceSum2(ss, red, tid);
    const float invS1 = 1.0f / S.x, invS2 = 1.0f / S.y;

    // ---- FFT2 pass 0, stage 1: product (Y shifted * g_Yf) on the fly -> X(skew) ----
    const float2* yf0 = g_Yf + d0 * IMG + row * 80;
    const float2* yf1 = g_Yf + d1 * IMG + row * 80;
    {
        const float2* ysh = Y + sft(row) * PITCH;
        float2* trow = X + row * PITCH;
#pragma unroll
        for (int m = 0; m < 2; m++) {
            const int n2 = j + 8 * m;
            float2 c[5];
#pragma unroll
            for (int n1 = 0; n1 < 5; n1++) {
                int col = 16 * n1 + n2;
                float2 mm = ysh[sft(col)];
                float A = mm.x * invS1, Bc = mm.y * invS2;
                float2 f0 = yf0[col], f1 = yf1[col];
                c[n1] = make_float2(A * f0.x - Bc * f1.y, A * f0.y + Bc * f1.x);
            }
            radix5_store<1>(c, n2, w80, trow);
        }
    }
    __syncthreads();
    // ---- FFT2 pass 0, stage 2: X(skew) -> Y ----
    if (j < 5) {
        const float2* trow = X + row * PITCH;
        const int k1 = j;
        float2 v[16];
#pragma unroll
        for (int t = 0; t < 16; t++) v[t] = trow[k1 * 16 + ((t + k1) & 15)];
        fft16r<1>(v);
#pragma unroll
        for (int k2 = 0; k2 < 16; k2++) Y[(k1 + 5 * k2) * PITCH + row] = v[k2];
    }
    __syncthreads();
    // ---- FFT2 pass 1, stage 1: Y -> X(skew) ----
    {
        const float2* s = Y + row * PITCH;
        float2* trow = X + row * PITCH;
#pragma unroll
        for (int m = 0; m < 2; m++) {
            const int n2 = j + 8 * m;
            float2 c[5];
#pragma unroll
            for (int n1 = 0; n1 < 5; n1++) c[n1] = s[16 * n1 + n2];
            radix5_store<1>(c, n2, w80, trow);
        }
    }
    __syncthreads();
    // ---- FFT2 pass 1, stage 2 fused with loss: no store ----
    float2 aa = make_float2(0.f, 0.f);
    if (j < 5) {
        const float2* trow = X + row * PITCH;
        const int k1 = j;
        float2 v[16];
#pragma unroll
        for (int t = 0; t < 16; t++) v[t] = trow[k1 * 16 + ((t + k1) & 15)];
        fft16r<1>(v);
        const int yj = sft(row);
        const float* y0 = y + d0 * IMG;
        const float* y1 = y + d1 * IMG;
#pragma unroll
        for (int k2 = 0; k2 < 16; k2++) {
            int iF = k1 + 5 * k2;
            int yi = sft(iF);
            float yv0 = y0[yi * 80 + yj];
            float yv1 = y1[yi * 80 + yj];
            float df0 = yv0 - fabsf(v[k2].x) * (1.0f / 6400.0f);
            float df1 = yv1 - fabsf(v[k2].y) * (1.0f / 6400.0f);
            aa.x += df0 * df0;
            aa.y += df1 * df1;
        }
    }
    float2 tt = blockReduceSum2(aa, red, tid);
    if (tid == 0) {
        g_partial[pd0] = tt.x;
        g_partial[pd1] = tt.y;
    }
}

// ---------------- kernel 3: reduce + argmin ----------------
__global__ void argmin_kernel(const float* __restrict__ params, float* __restrict__ out) {
    __shared__ float sl[NPARAMS];
    __shared__ int   si[NPARAMS];
    int tid = threadIdx.x;
    float s = 0.f;
    for (int d = 0; d < NDELAYS; d++) s += g_partial[tid * NDELAYS + d];
    float loss = s / (float)(NDELAYS * IMG);
    sl[tid] = loss; si[tid] = tid;
    __syncthreads();
    for (int st = 128; st > 0; st >>= 1) {
        if (tid < st) {
            float lo = sl[tid + st];
            if (lo < sl[tid] || (lo == sl[tid] && si[tid + st] < si[tid])) {
                sl[tid] = lo; si[tid] = si[tid + st];
            }
        }
        __syncthreads();
    }
    if (tid == 0) {
        g_best = si[0];
        out[X_FLOATS + TF_REAL + 0] = gld(params, (long long)si[0] * 3 + 0, 767);
        out[X_FLOATS + TF_REAL + 1] = gld(params, (long long)si[0] * 3 + 1, 767);
        out[X_FLOATS + TF_REAL + 2] = gld(params, (long long)si[0] * 3 + 2, 767);
        out[X_FLOATS + TF_REAL + 3] = sl[0];
    }
}

// ---------------- kernel 4: copy best TF (real floats) ----------------
__global__ void copytf_kernel(const float* __restrict__ tf, float* __restrict__ out) {
    long long base = (long long)g_best * TF_REAL;
    for (int i = blockIdx.x * blockDim.x + threadIdx.x; i < TF_REAL; i += gridDim.x * blockDim.x)
        out[X_FLOATS + i] = gld(tf, base + i, TF_TOTAL - 1);
}

// ---------------- kernel 5: best_x (Wiener deconv for winner), 32 blocks, 640 threads ----------------
__global__ void __launch_bounds__(NTHR2, 2) bestx_kernel(const float* __restrict__ tf, float* __restrict__ out) {
    extern __shared__ float sm[];
    float2* A = (float2*)sm;
    float2* B = A + NPTS * PITCH;
    float2* w80 = B + NPTS * PITCH;
    float* red = (float*)(w80 + 80);
    int tid = threadIdx.x;
    int d = blockIdx.x;
    fill_w80(w80, tid);
    long long base = ((long long)g_best * NDELAYS + d) * IMG;
    for (int idx = tid; idx < IMG; idx += NTHR2)
        A[(idx / 80) * PITCH + (idx % 80)] = make_float2(gld(tf, base + idx, TF_TOTAL - 1), 0.f);
    __syncthreads();
    fft2d80_8<1>(A, B, w80, tid >> 3, tid & 7);
    float s = 0.f;
    for (int idx = tid; idx < IMG; idx += NTHR2) {
        float2 v = A[(idx / 80) * PITCH + (idx % 80)];
        s += sqrtf(v.x * v.x + v.y * v.y);
    }
    float S = blockReduceSum(s, red, tid);
    float invS = 1.0f / S;
    for (int idx = tid; idx < IMG; idx += NTHR2) {
        int i = idx / 80, j = idx % 80;
        int si = sft(i), sj = sft(j);
        float2 a = A[si * PITCH + sj];
        B[i * PITCH + j] = make_float2(sqrtf(a.x * a.x + a.y * a.y) * invS, 0.f);
    }
    __syncthreads();
    fft2d80_8<-1>(B, A, w80, tid >> 3, tid & 7);   // H = fft2(psf)
    const float2* yf = g_Yf + d * IMG;
    for (int idx = tid; idx < IMG; idx += NTHR2) {
        int i = idx / 80, j = idx % 80;
        float2 h = B[i * PITCH + j];
        float2 f = yf[idx];
        float den = h.x * h.x + h.y * h.y + LAMBDA;
        B[i * PITCH + j] = make_float2((h.x * f.x + h.y * f.y) / den,
                                       (h.x * f.y - h.y * f.x) / den);
    }
    __syncthreads();
    fft2d80_8<1>(B, A, w80, tid >> 3, tid & 7);
    for (int idx = tid; idx < IMG; idx += NTHR2) {
        int i = idx / 80, j = idx % 80;
        int si = sft(i), sj = sft(j);
        float2 v = B[si * PITCH + sj];
        out[d * IMG + idx] = sqrtf(v.x * v.x + v.y * v.y) * (1.0f / 6400.0f);
    }
}

// ---------------- launcher ----------------
extern "C" void kernel_launch(void* const* d_in, const int* in_sizes, int n_in,
                              void* d_out, int out_size) {
    (void)in_sizes; (void)out_size;
    if (n_in < 3 || d_in == nullptr || d_out == nullptr) return;

    const float* y      = (const float*)d_in[0];   // 204800 floats
    const float* tf     = (const float*)d_in[1];   // 52428800 floats (TF real: cos(k(d-w)))
    const float* params = (const float*)d_in[2];   // 768 floats
    float* out = (float*)d_out;                    // 409604 floats: [x | tf | params | loss]

    cudaFuncSetAttribute(yf_kernel,    cudaFuncAttributeMaxDynamicSharedMemorySize, (int)SMEM_BYTES);
    cudaFuncSetAttribute(loss_kernel,  cudaFuncAttributeMaxDynamicSharedMemorySize, (int)SMEM_BYTES);
    cudaFuncSetAttribute(bestx_kernel, cudaFuncAttributeMaxDynamicSharedMemorySize, (int)SMEM_BYTES);

    yf_kernel<<<NDELAYS, NTHR2, SMEM_BYTES>>>(y);
    loss_kernel<<<NPARAMS * NDELAYS / 2, NTHR2, SMEM_BYTES>>>(tf, y);
    argmin_kernel<<<1, NPARAMS>>>(params, out);
    copytf_kernel<<<256, 256>>>(tf, out);
    bestx_kernel<<<NDELAYS, NTHR2, SMEM_BYTES>>>(tf, out);
}

// round 16
// speedup vs baseline: 4.3891x; 1.0967x over previous
#include <cuda_runtime.h>

#define NPTS 80
#define PITCH 88                        // 88 mod 16 == 8 -> conflict-free with 8-thread/row layout
#define NDELAYS 32
#define NPARAMS 256
#define IMG 6400
#define LAMBDA 0.03f
#define X_FLOATS (NDELAYS*IMG)          // 204800 floats for best_x
#define TF_REAL  (NDELAYS*IMG)          // 204800 floats for best tf (real-valued)
#define TF_TOTAL ((long long)NPARAMS * NDELAYS * IMG)   // 52428800 floats
#define NTHR2 640                       // 8 threads per row

// ---------------- workspace ----------------
__device__ float2 g_Yf[NDELAYS * IMG];
__device__ float  g_partial[NPARAMS * NDELAYS];
__device__ int    g_best;

__device__ __forceinline__ float gld(const float* p, long long i, long long imax) {
    return (i >= 0 && i <= imax) ? p[i] : 0.f;
}
__device__ __forceinline__ int sft(int i) { return (i >= 40) ? i - 40 : i + 40; }

// ---------------- 16-point FFT in registers ----------------
template<int U>
__device__ __forceinline__ void fft16r(float2* v) {
    const float C16[8] = {1.f, 0.9238795325112867f, 0.7071067811865476f, 0.3826834323650898f,
                          0.f, -0.3826834323650898f, -0.7071067811865476f, -0.9238795325112867f};
    const float S16[8] = {0.f, 0.3826834323650898f, 0.7071067811865476f, 0.9238795325112867f,
                          1.f, 0.9238795325112867f, 0.7071067811865476f, 0.3826834323650898f};
    float2 t;
    t = v[1];  v[1]  = v[8];  v[8]  = t;
    t = v[2];  v[2]  = v[4];  v[4]  = t;
    t = v[3];  v[3]  = v[12]; v[12] = t;
    t = v[5];  v[5]  = v[10]; v[10] = t;
    t = v[7];  v[7]  = v[14]; v[14] = t;
    t = v[11]; v[11] = v[13]; v[13] = t;
#pragma unroll
    for (int len = 2; len <= 16; len <<= 1) {
        const int half = len >> 1;
        const int step = 16 / len;
#pragma unroll
        for (int i = 0; i < 16; i += len) {
#pragma unroll
            for (int j = 0; j < half; j++) {
                float wc = C16[j * step];
                float ws = (float)U * S16[j * step];
                float2 a = v[i + j], b = v[i + j + half];
                float tr = b.x * wc - b.y * ws;
                float ti = b.x * ws + b.y * wc;
                v[i + j]        = make_float2(a.x + tr, a.y + ti);
                v[i + j + half] = make_float2(a.x - tr, a.y - ti);
            }
        }
    }
}

// ---------------- Winograd radix-5 + W80 twiddle + skewed store ----------------
template<int U>
__device__ __forceinline__ void radix5_store(const float2 c[5], int n2, const float2* w80, float2* trow) {
    const float uC2 = 0.5590169943749475f;
    const float uS1 = 0.9510565162951535f;
    const float uS2 = 0.5877852522924731f;
    const float u = (float)U;
    float2 p1 = make_float2(c[1].x + c[4].x, c[1].y + c[4].y);
    float2 p2 = make_float2(c[2].x + c[3].x, c[2].y + c[3].y);
    float2 m3 = make_float2(c[1].x - c[4].x, c[1].y - c[4].y);
    float2 m4 = make_float2(c[2].x - c[3].x, c[2].y - c[3].y);
    float2 t5 = make_float2(p1.x + p2.x, p1.y + p2.y);
    float2 aa = make_float2(c[0].x - 0.25f * t5.x, c[0].y - 0.25f * t5.y);
    float2 bb = make_float2(uC2 * (p1.x - p2.x), uC2 * (p1.y - p2.y));
    float2 Y1 = make_float2(aa.x + bb.x, aa.y + bb.y);
    float2 Y2 = make_float2(aa.x - bb.x, aa.y - bb.y);
    float2 cc = make_float2(uS1 * m3.x + uS2 * m4.x, uS1 * m3.y + uS2 * m4.y);
    float2 dd = make_float2(uS2 * m3.x - uS1 * m4.x, uS2 * m3.y - uS1 * m4.y);
    float2 Xk[5];
    Xk[0] = make_float2(c[0].x + t5.x, c[0].y + t5.y);
    Xk[1] = make_float2(Y1.x - u * cc.y, Y1.y + u * cc.x);
    Xk[4] = make_float2(Y1.x + u * cc.y, Y1.y - u * cc.x);
    Xk[2] = make_float2(Y2.x - u * dd.y, Y2.y + u * dd.x);
    Xk[3] = make_float2(Y2.x + u * dd.y, Y2.y - u * dd.x);
    trow[n2] = Xk[0];
#pragma unroll
    for (int k = 1; k < 5; k++) {
        float wc = w80[n2 * k].x, ws = (float)U * w80[n2 * k].y;
        trow[k * 16 + ((n2 + k) & 15)] =
            make_float2(Xk[k].x * wc - Xk[k].y * ws, Xk[k].x * ws + Xk[k].y * wc);
    }
}

// ---------------- 80x80 2D FFT, 8 threads/row (640 threads), in place on X, T scratch ----------------
template<int U>
__device__ void fft2d80_8(float2* X, float2* T, const float2* w80, int row, int j) {
#pragma unroll
    for (int pass = 0; pass < 2; ++pass) {
        {
            const float2* s = X + row * PITCH;
            float2* trow = T + row * PITCH;
#pragma unroll
            for (int m = 0; m < 2; m++) {
                const int n2 = j + 8 * m;
                float2 c[5];
#pragma unroll
                for (int n1 = 0; n1 < 5; n1++) c[n1] = s[16 * n1 + n2];
                radix5_store<U>(c, n2, w80, trow);
            }
        }
        __syncthreads();
        if (j < 5) {
            const float2* trow = T + row * PITCH;
            const int k1 = j;
            float2 v[16];
#pragma unroll
            for (int t = 0; t < 16; t++) v[t] = trow[k1 * 16 + ((t + k1) & 15)];
            fft16r<U>(v);
#pragma unroll
            for (int k2 = 0; k2 < 16; k2++) X[(k1 + 5 * k2) * PITCH + row] = v[k2];
        }
        __syncthreads();
    }
}

// ---------------- block reduces ----------------
__device__ float blockReduceSum(float v, float* red, int tid) {
#pragma unroll
    for (int o = 16; o > 0; o >>= 1) v += __shfl_down_sync(0xffffffffu, v, o);
    if ((tid & 31) == 0) red[tid >> 5] = v;
    __syncthreads();
    if (tid == 0) {
        float s = 0.f;
        for (int w = 0; w < (int)(blockDim.x >> 5); w++) s += red[w];
        red[0] = s;
    }
    __syncthreads();
    float r = red[0];
    __syncthreads();
    return r;
}

__device__ float2 blockReduceSum2(float2 v, float* red, int tid) {
#pragma unroll
    for (int o = 16; o > 0; o >>= 1) {
        v.x += __shfl_down_sync(0xffffffffu, v.x, o);
        v.y += __shfl_down_sync(0xffffffffu, v.y, o);
    }
    if ((tid & 31) == 0) { red[2 * (tid >> 5)] = v.x; red[2 * (tid >> 5) + 1] = v.y; }
    __syncthreads();
    if (tid == 0) {
        float sx = 0.f, sy = 0.f;
        for (int w = 0; w < (int)(blockDim.x >> 5); w++) { sx += red[2 * w]; sy += red[2 * w + 1]; }
        red[0] = sx; red[1] = sy;
    }
    __syncthreads();
    float2 r = make_float2(red[0], red[1]);
    __syncthreads();
    return r;
}

#define SMEM_F2 (2 * NPTS * PITCH + 80)
#define SMEM_BYTES (SMEM_F2 * sizeof(float2) + 64 * sizeof(float))

__device__ __forceinline__ void fill_w80(float2* w80, int tid) {
    if (tid < 80) {
        float sv, cv;
        sincospif((float)tid * (1.0f / 40.0f), &sv, &cv);
        w80[tid] = make_float2(cv, sv);
    }
}

// ---------------- kernel 1: Yf = fft2(y), 32 blocks, 640 threads ----------------
__global__ void __launch_bounds__(NTHR2, 2) yf_kernel(const float* __restrict__ y) {
    extern __shared__ float sm[];
    float2* A = (float2*)sm;
    float2* B = A + NPTS * PITCH;
    float2* w80 = B + NPTS * PITCH;
    int tid = threadIdx.x;
    int d = blockIdx.x;
    fill_w80(w80, tid);
    for (int idx = tid; idx < IMG; idx += NTHR2)
        A[(idx / 80) * PITCH + (idx % 80)] = make_float2(gld(y, (long long)d * IMG + idx, X_FLOATS - 1), 0.f);
    __syncthreads();
    fft2d80_8<-1>(A, B, w80, tid >> 3, tid & 7);
    for (int idx = tid; idx < IMG; idx += NTHR2)
        g_Yf[d * IMG + idx] = A[(idx / 80) * PITCH + (idx % 80)];
}

// ---------------- kernel 2: paired loss over two PARAMS at the SAME delay ----------------
// block b: d = b >> 7, q = b & 127; images (p0=2q, d) and (p1=2q+1, d).
// Same-d pairing halves g_Yf and y traffic (single plane reused for both images),
// and consecutive blocks share the same d -> y/yf planes stay L2-hot.
__global__ void __launch_bounds__(NTHR2, 2) loss_kernel(const float* __restrict__ tf, const float* __restrict__ y) {
    extern __shared__ float sm[];
    float2* X = (float2*)sm;
    float2* Y = X + NPTS * PITCH;
    float2* w80 = Y + NPTS * PITCH;
    float* red = (float*)(w80 + 80);
    const int tid = threadIdx.x;
    const int row = tid >> 3;       // 0..79
    const int j   = tid & 7;        // 0..7
    const int q = blockIdx.x & 127;
    const int d = blockIdx.x >> 7;
    const int pd0 = 64 * q + d;           // (p=2q, d)
    const int pd1 = pd0 + 32;             // (p=2q+1, d)
    fill_w80(w80, tid);
    __syncthreads();
    const long long b0 = (long long)pd0 * IMG + row * 80;
    const long long b1 = (long long)pd1 * IMG + row * 80;

    // ---- FFT1 pass 0, stage 1: read TF directly from global ----
    {
        float2* trow = Y + row * PITCH;
#pragma unroll
        for (int m = 0; m < 2; m++) {
            const int n2 = j + 8 * m;
            float2 c[5];
#pragma unroll
            for (int n1 = 0; n1 < 5; n1++) {
                int col = 16 * n1 + n2;
                c[n1] = make_float2(tf[b0 + col], tf[b1 + col]);
            }
            radix5_store<1>(c, n2, w80, trow);
        }
    }
    __syncthreads();
    // ---- FFT1 pass 0, stage 2 ----
    if (j < 5) {
        const float2* trow = Y + row * PITCH;
        const int k1 = j;
        float2 v[16];
#pragma unroll
        for (int t = 0; t < 16; t++) v[t] = trow[k1 * 16 + ((t + k1) & 15)];
        fft16r<1>(v);
#pragma unroll
        for (int k2 = 0; k2 < 16; k2++) X[(k1 + 5 * k2) * PITCH + row] = v[k2];
    }
    __syncthreads();
    // ---- FFT1 pass 1, stage 1 ----
    {
        const float2* s = X + row * PITCH;
        float2* trow = Y + row * PITCH;
#pragma unroll
        for (int m = 0; m < 2; m++) {
            const int n2 = j + 8 * m;
            float2 c[5];
#pragma unroll
            for (int n1 = 0; n1 < 5; n1++) c[n1] = s[16 * n1 + n2];
            radix5_store<1>(c, n2, w80, trow);
        }
    }
    __syncthreads();
    // ---- FFT1 pass 1, stage 2 ----
    if (j < 5) {
        const float2* trow = Y + row * PITCH;
        const int k1 = j;
        float2 v[16];
#pragma unroll
        for (int t = 0; t < 16; t++) v[t] = trow[k1 * 16 + ((t + k1) & 15)];
        fft16r<1>(v);
#pragma unroll
        for (int k2 = 0; k2 < 16; k2++) X[(k1 + 5 * k2) * PITCH + row] = v[k2];
    }
    __syncthreads();

    // ---- phase A: psf magnitudes (half-domain, even symmetry) X -> Y; sums ----
    float2 ss = make_float2(0.f, 0.f);
    for (int idx = tid; idx < 41 * 80; idx += NTHR2) {
        int i = idx / 80, jc = idx % 80;
        int ni = (i == 0) ? 0 : 80 - i;
        int nj = (jc == 0) ? 0 : 80 - jc;
        float2 Zk = X[i * PITCH + jc];
        float2 Zm = X[ni * PITCH + nj];
        float g1r = 0.5f * (Zk.x + Zm.x), g1i = 0.5f * (Zk.y - Zm.y);
        float g2r = 0.5f * (Zk.y + Zm.y), g2i = 0.5f * (Zm.x - Zk.x);
        float m1 = sqrtf(g1r * g1r + g1i * g1i);
        float m2 = sqrtf(g2r * g2r + g2i * g2i);
        float2 mm = make_float2(m1, m2);
        Y[i * PITCH + jc] = mm;
        Y[ni * PITCH + nj] = mm;
        float wgt = (i >= 1 && i <= 39) ? 2.f : 1.f;
        ss.x += wgt * m1; ss.y += wgt * m2;
    }
    float2 S = blockReduceSum2(ss, red, tid);
    const float invS1 = 1.0f / S.x, invS2 = 1.0f / S.y;

    // ---- FFT2 pass 0, stage 1: product (Y shifted * g_Yf[d]) on the fly -> X(skew) ----
    const float2* yfd = g_Yf + d * IMG + row * 80;
    {
        const float2* ysh = Y + sft(row) * PITCH;
        float2* trow = X + row * PITCH;
#pragma unroll
        for (int m = 0; m < 2; m++) {
            const int n2 = j + 8 * m;
            float2 c[5];
#pragma unroll
            for (int n1 = 0; n1 < 5; n1++) {
                int col = 16 * n1 + n2;
                float2 mm = ysh[sft(col)];
                float A = mm.x * invS1, Bc = mm.y * invS2;
                float2 f = yfd[col];                 // same delay for both images
                c[n1] = make_float2(A * f.x - Bc * f.y, A * f.y + Bc * f.x);
            }
            radix5_store<1>(c, n2, w80, trow);
        }
    }
    __syncthreads();
    // ---- FFT2 pass 0, stage 2: X(skew) -> Y ----
    if (j < 5) {
        const float2* trow = X + row * PITCH;
        const int k1 = j;
        float2 v[16];
#pragma unroll
        for (int t = 0; t < 16; t++) v[t] = trow[k1 * 16 + ((t + k1) & 15)];
        fft16r<1>(v);
#pragma unroll
        for (int k2 = 0; k2 < 16; k2++) Y[(k1 + 5 * k2) * PITCH + row] = v[k2];
    }
    __syncthreads();
    // ---- FFT2 pass 1, stage 1: Y -> X(skew) ----
    {
        const float2* s = Y + row * PITCH;
        float2* trow = X + row * PITCH;
#pragma unroll
        for (int m = 0; m < 2; m++) {
            const int n2 = j + 8 * m;
            float2 c[5];
#pragma unroll
            for (int n1 = 0; n1 < 5; n1++) c[n1] = s[16 * n1 + n2];
            radix5_store<1>(c, n2, w80, trow);
        }
    }
    __syncthreads();
    // ---- FFT2 pass 1, stage 2 fused with loss (single y plane, two diffs) ----
    float2 aa = make_float2(0.f, 0.f);
    if (j < 5) {
        const float2* trow = X + row * PITCH;
        const int k1 = j;
        float2 v[16];
#pragma unroll
        for (int t = 0; t < 16; t++) v[t] = trow[k1 * 16 + ((t + k1) & 15)];
        fft16r<1>(v);
        const int yj = sft(row);
        const float* yd = y + d * IMG;
#pragma unroll
        for (int k2 = 0; k2 < 16; k2++) {
            int iF = k1 + 5 * k2;
            int yi = sft(iF);
            float yv = yd[yi * 80 + yj];             // loaded once, used twice
            float df0 = yv - fabsf(v[k2].x) * (1.0f / 6400.0f);
            float df1 = yv - fabsf(v[k2].y) * (1.0f / 6400.0f);
            aa.x += df0 * df0;
            aa.y += df1 * df1;
        }
    }
    float2 tt = blockReduceSum2(aa, red, tid);
    if (tid == 0) {
        g_partial[pd0] = tt.x;
        g_partial[pd1] = tt.y;
    }
}

// ---------------- kernel 3: reduce + argmin ----------------
__global__ void argmin_kernel(const float* __restrict__ params, float* __restrict__ out) {
    __shared__ float sl[NPARAMS];
    __shared__ int   si[NPARAMS];
    int tid = threadIdx.x;
    float s = 0.f;
    for (int d = 0; d < NDELAYS; d++) s += g_partial[tid * NDELAYS + d];
    float loss = s / (float)(NDELAYS * IMG);
    sl[tid] = loss; si[tid] = tid;
    __syncthreads();
    for (int st = 128; st > 0; st >>= 1) {
        if (tid < st) {
            float lo = sl[tid + st];
            if (lo < sl[tid] || (lo == sl[tid] && si[tid + st] < si[tid])) {
                sl[tid] = lo; si[tid] = si[tid + st];
            }
        }
        __syncthreads();
    }
    if (tid == 0) {
        g_best = si[0];
        out[X_FLOATS + TF_REAL + 0] = gld(params, (long long)si[0] * 3 + 0, 767);
        out[X_FLOATS + TF_REAL + 1] = gld(params, (long long)si[0] * 3 + 1, 767);
        out[X_FLOATS + TF_REAL + 2] = gld(params, (long long)si[0] * 3 + 2, 767);
        out[X_FLOATS + TF_REAL + 3] = sl[0];
    }
}

// ---------------- kernel 4: copy best TF (real floats) ----------------
__global__ void copytf_kernel(const float* __restrict__ tf, float* __restrict__ out) {
    long long base = (long long)g_best * TF_REAL;
    for (int i = blockIdx.x * blockDim.x + threadIdx.x; i < TF_REAL; i += gridDim.x * blockDim.x)
        out[X_FLOATS + i] = gld(tf, base + i, TF_TOTAL - 1);
}

// ---------------- kernel 5: best_x (Wiener deconv for winner), 32 blocks, 640 threads ----------------
__global__ void __launch_bounds__(NTHR2, 2) bestx_kernel(const float* __restrict__ tf, float* __restrict__ out) {
    extern __shared__ float sm[];
    float2* A = (float2*)sm;
    float2* B = A + NPTS * PITCH;
    float2* w80 = B + NPTS * PITCH;
    float* red = (float*)(w80 + 80);
    int tid = threadIdx.x;
    int d = blockIdx.x;
    fill_w80(w80, tid);
    long long base = ((long long)g_best * NDELAYS + d) * IMG;
    for (int idx = tid; idx < IMG; idx += NTHR2)
        A[(idx / 80) * PITCH + (idx % 80)] = make_float2(gld(tf, base + idx, TF_TOTAL - 1), 0.f);
    __syncthreads();
    fft2d80_8<1>(A, B, w80, tid >> 3, tid & 7);
    float s = 0.f;
    for (int idx = tid; idx < IMG; idx += NTHR2) {
        float2 v = A[(idx / 80) * PITCH + (idx % 80)];
        s += sqrtf(v.x * v.x + v.y * v.y);
    }
    float S = blockReduceSum(s, red, tid);
    float invS = 1.0f / S;
    for (int idx = tid; idx < IMG; idx += NTHR2) {
        int i = idx / 80, j = idx % 80;
        int si = sft(i), sj = sft(j);
        float2 a = A[si * PITCH + sj];
        B[i * PITCH + j] = make_float2(sqrtf(a.x * a.x + a.y * a.y) * invS, 0.f);
    }
    __syncthreads();
    fft2d80_8<-1>(B, A, w80, tid >> 3, tid & 7);   // H = fft2(psf)
    const float2* yf = g_Yf + d * IMG;
    for (int idx = tid; idx < IMG; idx += NTHR2) {
        int i = idx / 80, j = idx % 80;
        float2 h = B[i * PITCH + j];
        float2 f = yf[idx];
        float den = h.x * h.x + h.y * h.y + LAMBDA;
        B[i * PITCH + j] = make_float2((h.x * f.x + h.y * f.y) / den,
                                       (h.x * f.y - h.y * f.x) / den);
    }
    __syncthreads();
    fft2d80_8<1>(B, A, w80, tid >> 3, tid & 7);
    for (int idx = tid; idx < IMG; idx += NTHR2) {
        int i = idx / 80, j = idx % 80;
        int si = sft(i), sj = sft(j);
        float2 v = B[si * PITCH + sj];
        out[d * IMG + idx] = sqrtf(v.x * v.x + v.y * v.y) * (1.0f / 6400.0f);
    }
}

// ---------------- launcher ----------------
extern "C" void kernel_launch(void* const* d_in, const int* in_sizes, int n_in,
                              void* d_out, int out_size) {
    (void)in_sizes; (void)out_size;
    if (n_in < 3 || d_in == nullptr || d_out == nullptr) return;

    const float* y      = (const float*)d_in[0];   // 204800 floats
    const float* tf     = (const float*)d_in[1];   // 52428800 floats (TF real: cos(k(d-w)))
    const float* params = (const float*)d_in[2];   // 768 floats
    float* out = (float*)d_out;                    // 409604 floats: [x | tf | params | loss]

    cudaFuncSetAttribute(yf_kernel,    cudaFuncAttributeMaxDynamicSharedMemorySize, (int)SMEM_BYTES);
    cudaFuncSetAttribute(loss_kernel,  cudaFuncAttributeMaxDynamicSharedMemorySize, (int)SMEM_BYTES);
    cudaFuncSetAttribute(bestx_kernel, cudaFuncAttributeMaxDynamicSharedMemorySize, (int)SMEM_BYTES);

    yf_kernel<<<NDELAYS, NTHR2, SMEM_BYTES>>>(y);
    loss_kernel<<<NPARAMS * NDELAYS / 2, NTHR2, SMEM_BYTES>>>(tf, y);
    argmin_kernel<<<1, NPARAMS>>>(params, out);
    copytf_kernel<<<256, 256>>>(tf, out);
    bestx_kernel<<<NDELAYS, NTHR2, SMEM_BYTES>>>(tf, out);
}